// round 14
// baseline (speedup 1.0000x reference)
#include <cuda_runtime.h>
#include <cuda_bf16.h>
#include <cuda_fp16.h>
#include <cstdint>

#define NN 100000
#define EE 3200000
#define K1 512
#define HD 256
#define FD 64

// ---------------- scratch -----------------------------------------------------
__device__ __align__(16) __half g_XW0h[NN * HD];    // X @ W0 fp16 (51 MB)
__device__ __align__(16) float g_H1[NN * HD];       // relu(A @ XW0) fp32
__device__ __align__(16) float g_H1W1[NN * FD];     // logits precursor fp32
__device__ int   g_rowptr[NN + 1];
__device__ int   g_cursor[NN];
__device__ int   g_cnt[NN];
__device__ __align__(16) int2 g_cedge[EE];          // (col, valbits) fused
__device__ __align__(16) __half g_W0t_h[HD * K1];   // W0^T fp16 [256][512]
__device__ __align__(16) __nv_bfloat16 g_W1t_hi[FD * HD];  // W1^T split [64][256]
__device__ __align__(16) __nv_bfloat16 g_W1t_lo[FD * HD];

// ---------------- helpers ------------------------------------------------------
__device__ __forceinline__ uint32_t smem_u32(const void* p) {
    uint32_t a;
    asm("{ .reg .u64 t; cvta.to.shared.u64 t, %1; cvt.u32.u64 %0, t; }" : "=r"(a) : "l"(p));
    return a;
}
__device__ __forceinline__ void ldmx4(uint32_t* d, uint32_t addr) {
    asm volatile("ldmatrix.sync.aligned.m8n8.x4.shared.b16 {%0,%1,%2,%3}, [%4];"
                 : "=r"(d[0]), "=r"(d[1]), "=r"(d[2]), "=r"(d[3]) : "r"(addr));
}
__device__ __forceinline__ void mma16816h(float* c, const uint32_t* a, uint32_t b0, uint32_t b1) {
    asm volatile("mma.sync.aligned.m16n8k16.row.col.f32.f16.f16.f32 "
                 "{%0,%1,%2,%3}, {%4,%5,%6,%7}, {%8,%9}, {%0,%1,%2,%3};"
                 : "+f"(c[0]), "+f"(c[1]), "+f"(c[2]), "+f"(c[3])
                 : "r"(a[0]), "r"(a[1]), "r"(a[2]), "r"(a[3]), "r"(b0), "r"(b1));
}
__device__ __forceinline__ void mma16816b(float* c, const uint32_t* a, uint32_t b0, uint32_t b1) {
    asm volatile("mma.sync.aligned.m16n8k16.row.col.f32.bf16.bf16.f32 "
                 "{%0,%1,%2,%3}, {%4,%5,%6,%7}, {%8,%9}, {%0,%1,%2,%3};"
                 : "+f"(c[0]), "+f"(c[1]), "+f"(c[2]), "+f"(c[3])
                 : "r"(a[0]), "r"(a[1]), "r"(a[2]), "r"(a[3]), "r"(b0), "r"(b1));
}

// ---------------- CSR build -----------------------------------------------------
__global__ void zero_cnt_kernel() {
    int i = blockIdx.x * blockDim.x + threadIdx.x;
    if (i < NN) g_cnt[i] = 0;
}
__global__ void hist_kernel(const int4* __restrict__ rows4) {
    int i = blockIdx.x * blockDim.x + threadIdx.x;
    if (i < EE / 4) {
        int4 r = rows4[i];
        atomicAdd(&g_cnt[r.x], 1);
        atomicAdd(&g_cnt[r.y], 1);
        atomicAdd(&g_cnt[r.z], 1);
        atomicAdd(&g_cnt[r.w], 1);
    }
}
__global__ void __launch_bounds__(1024) scan_kernel() {
    __shared__ int wsum[32];
    int tid = threadIdx.x;
    const int PER = 98;
    int base = tid * PER;
    int s = 0;
    for (int j = 0; j < PER; j++) {
        int i = base + j;
        if (i < NN) s += g_cnt[i];
    }
    int lane = tid & 31, wid = tid >> 5;
    int x = s;
    #pragma unroll
    for (int o = 1; o < 32; o <<= 1) {
        int t = __shfl_up_sync(0xffffffffu, x, o);
        if (lane >= o) x += t;
    }
    if (lane == 31) wsum[wid] = x;
    __syncthreads();
    if (wid == 0) {
        int w = wsum[lane];
        #pragma unroll
        for (int o = 1; o < 32; o <<= 1) {
            int t = __shfl_up_sync(0xffffffffu, w, o);
            if (lane >= o) w += t;
        }
        wsum[lane] = w;
    }
    __syncthreads();
    int excl = x - s + (wid > 0 ? wsum[wid - 1] : 0);
    int run = excl;
    for (int j = 0; j < PER; j++) {
        int i = base + j;
        if (i < NN) {
            g_rowptr[i] = run;
            g_cursor[i] = run;
            run += g_cnt[i];
        }
    }
    if (tid == 1023) g_rowptr[NN] = run;
}
__global__ void scatter_kernel(const int* __restrict__ rows,
                               const int* __restrict__ cols,
                               const float* __restrict__ vals) {
    int i = blockIdx.x * blockDim.x + threadIdx.x;
    if (i < EE) {
        int r = rows[i];
        int p = atomicAdd(&g_cursor[r], 1);
        g_cedge[p] = make_int2(cols[i], __float_as_int(vals[i]));
    }
}

// ---------------- weight prep -----------------------------------------------------
__global__ void w0_half_kernel(const float* __restrict__ W0) {
    int i = blockIdx.x * blockDim.x + threadIdx.x;
    if (i < K1 * HD) {
        int k = i / HD, n = i % HD;
        g_W0t_h[n * K1 + k] = __float2half(W0[i]);
    }
}
__global__ void w1_split_kernel(const float* __restrict__ W1) {
    int i = blockIdx.x * blockDim.x + threadIdx.x;
    if (i < HD * FD) {
        int k = i / FD, n = i % FD;
        float v = W1[i];
        __nv_bfloat16 h = __float2bfloat16(v);
        g_W1t_hi[n * HD + k] = h;
        g_W1t_lo[n * HD + k] = __float2bfloat16(v - __bfloat162float(h));
    }
}

// ---------------- GEMM1 via mma.sync fp16, fp16 out ------------------------------
#define G1_KC   32
#define G1_NC   (K1 / G1_KC)
#define G1_STR  40
#define G1_BUF  20480                  // A 10240 | B 10240
#define G1_SMEM (2 * G1_BUF)

__global__ void __launch_bounds__(256, 2) gemm1_mma_kernel(const float* __restrict__ A) {
    extern __shared__ __align__(16) char smem[];
    uint32_t sb = smem_u32(smem);

    int tid  = threadIdx.x;
    int lane = tid & 31;
    int wid  = tid >> 5;
    int wm   = wid >> 2;
    int wn   = wid & 3;
    int row0 = blockIdx.x * 128;
    int col0 = blockIdx.y * 128;

    int a_row = tid >> 3;
    int a_kc  = (tid & 7) * 4;
    int b_row = tid >> 1;
    int b_kc  = (tid & 1) * 16;

    float4 aS[4];
    uint4  bS[2];

    uint32_t a_ld_off = (uint32_t)((wm * 64 + (lane & 15)) * G1_STR + ((lane >> 4) << 3)) * 2;
    uint32_t b_ld_off = (uint32_t)((wn * 32 + (lane & 7) + ((lane >> 4) << 3)) * G1_STR
                                   + (((lane >> 3) & 1) << 3)) * 2;

    float acc[4][4][4];
    #pragma unroll
    for (int i = 0; i < 4; i++)
        #pragma unroll
        for (int j = 0; j < 4; j++)
            #pragma unroll
            for (int t = 0; t < 4; t++) acc[i][j][t] = 0.f;

    auto load_stage = [&](int kt) {
        #pragma unroll
        for (int p = 0; p < 4; p++) {
            int r = row0 + a_row + p * 32;
            aS[p] = (r < NN)
                ? *reinterpret_cast<const float4*>(A + (size_t)r * K1 + kt + a_kc)
                : make_float4(0.f, 0.f, 0.f, 0.f);
        }
        int n = col0 + b_row;
        #pragma unroll
        for (int p = 0; p < 2; p++)
            bS[p] = *reinterpret_cast<const uint4*>(g_W0t_h + (size_t)n * K1 + kt + b_kc + p * 8);
    };

    auto store_stage = [&](int buf) {
        char* base = smem + buf * G1_BUF;
        #pragma unroll
        for (int p = 0; p < 4; p++) {
            float4 v = aS[p];
            __half2 h01 = __floats2half2_rn(v.x, v.y);
            __half2 h23 = __floats2half2_rn(v.z, v.w);
            uint32_t off = (uint32_t)((a_row + p * 32) * G1_STR + a_kc) * 2;
            *reinterpret_cast<uint2*>(base + off) =
                make_uint2(*(uint32_t*)&h01, *(uint32_t*)&h23);
        }
        #pragma unroll
        for (int p = 0; p < 2; p++) {
            uint32_t off = (uint32_t)(b_row * G1_STR + b_kc + p * 8) * 2;
            *reinterpret_cast<uint4*>(base + 10240 + off) = bS[p];
        }
    };

    auto compute = [&](int buf) {
        uint32_t ab = sb + buf * G1_BUF;
        #pragma unroll
        for (int ks = 0; ks < 2; ks++) {
            uint32_t kso = (uint32_t)(ks * 16) * 2;
            uint32_t ah[4][4], bh[4][2];
            #pragma unroll
            for (int i = 0; i < 4; i++) {
                uint32_t ao = ab + a_ld_off + kso + (uint32_t)(i * 16 * G1_STR) * 2;
                ldmx4(ah[i], ao);
            }
            #pragma unroll
            for (int j2 = 0; j2 < 2; j2++) {
                uint32_t bo = ab + 10240 + b_ld_off + kso + (uint32_t)(j2 * 16 * G1_STR) * 2;
                uint32_t t[4];
                ldmx4(t, bo);
                bh[j2 * 2][0] = t[0]; bh[j2 * 2][1] = t[1];
                bh[j2 * 2 + 1][0] = t[2]; bh[j2 * 2 + 1][1] = t[3];
            }
            #pragma unroll
            for (int i = 0; i < 4; i++)
                #pragma unroll
                for (int j = 0; j < 4; j++)
                    mma16816h(acc[i][j], ah[i], bh[j][0], bh[j][1]);
        }
    };

    load_stage(0);
    store_stage(0);
    __syncthreads();

    for (int c = 0; c < G1_NC; c++) {
        if (c + 1 < G1_NC) load_stage((c + 1) * G1_KC);
        compute(c & 1);
        if (c + 1 < G1_NC) store_stage((c + 1) & 1);
        __syncthreads();
    }

    #pragma unroll
    for (int i = 0; i < 4; i++) {
        int r0 = row0 + wm * 64 + i * 16 + (lane >> 2);
        #pragma unroll
        for (int j = 0; j < 4; j++) {
            int cidx = col0 + wn * 32 + j * 8 + (lane & 3) * 2;
            if (r0 < NN)
                *reinterpret_cast<__half2*>(g_XW0h + (size_t)r0 * HD + cidx) =
                    __floats2half2_rn(acc[i][j][0], acc[i][j][1]);
            if (r0 + 8 < NN)
                *reinterpret_cast<__half2*>(g_XW0h + (size_t)(r0 + 8) * HD + cidx) =
                    __floats2half2_rn(acc[i][j][2], acc[i][j][3]);
        }
    }
}

// ---------------- SpMM1: H1 = relu(A @ XW0h), shfl-distributed edges --------------
__device__ __forceinline__ void fmah8(float* acc, float v, const uint4& q) {
    const __half2* h = reinterpret_cast<const __half2*>(&q);
    #pragma unroll
    for (int t = 0; t < 4; t++) {
        float2 f = __half22float2(h[t]);
        acc[2 * t]     = fmaf(v, f.x, acc[2 * t]);
        acc[2 * t + 1] = fmaf(v, f.y, acc[2 * t + 1]);
    }
}

__global__ void __launch_bounds__(256) spmm1_relu_kernel() {
    int w    = (blockIdx.x * blockDim.x + threadIdx.x) >> 5;
    int lane = threadIdx.x & 31;
    if (w >= NN) return;

    int s = g_rowptr[w], e = g_rowptr[w + 1];
    const uint4* Yh = reinterpret_cast<const uint4*>(g_XW0h);

    float acc[8];
    #pragma unroll
    for (int t = 0; t < 8; t++) acc[t] = 0.f;

    int i = s;
    // fast path: 32 edges fetched coalesced (one LDG.64/lane), distributed via shfl
    for (; i + 32 <= e; i += 32) {
        long long ev = *reinterpret_cast<const long long*>(&g_cedge[i + lane]);
        #pragma unroll
        for (int g = 0; g < 4; g++) {
            float v[8];
            uint4 q[8];
            #pragma unroll
            for (int u = 0; u < 8; u++) {
                long long ed = __shfl_sync(0xffffffffu, ev, g * 8 + u);
                int col = (int)(ed & 0xffffffffll);
                v[u] = __int_as_float((int)(ed >> 32));
                q[u] = Yh[(size_t)col * 32 + lane];
            }
            #pragma unroll
            for (int u = 0; u < 8; u++) fmah8(acc, v[u], q[u]);
        }
    }
    // tail (<32 edges): coalesced fetch of remainder, shfl-distributed
    if (i < e) {
        int cnt = e - i;
        long long ev = 0;
        if (lane < cnt)
            ev = *reinterpret_cast<const long long*>(&g_cedge[i + lane]);
        for (int u = 0; u < cnt; u++) {
            long long ed = __shfl_sync(0xffffffffu, ev, u);
            int col = (int)(ed & 0xffffffffll);
            float v = __int_as_float((int)(ed >> 32));
            uint4 q = Yh[(size_t)col * 32 + lane];
            fmah8(acc, v, q);
        }
    }

    float* dst = g_H1 + (size_t)w * HD + lane * 8;
    *reinterpret_cast<float4*>(dst) =
        make_float4(fmaxf(acc[0], 0.f), fmaxf(acc[1], 0.f),
                    fmaxf(acc[2], 0.f), fmaxf(acc[3], 0.f));
    *reinterpret_cast<float4*>(dst + 4) =
        make_float4(fmaxf(acc[4], 0.f), fmaxf(acc[5], 0.f),
                    fmaxf(acc[6], 0.f), fmaxf(acc[7], 0.f));
}

// ---------------- GEMM2 via mma.sync split-bf16 (3 products): fp32 in/out ---------
#define G2_KC   32
#define G2_NC   (HD / G2_KC)          // 8
#define G2_STR  40
#define G2_AH   0
#define G2_AL   10240
#define G2_BH   20480
#define G2_BL   25600
#define G2_BUF  30720
#define G2_SMEM (2 * G2_BUF)

__global__ void __launch_bounds__(256) gemm2_mma_kernel() {
    extern __shared__ __align__(16) char smem[];
    uint32_t sb = smem_u32(smem);

    int tid  = threadIdx.x;
    int lane = tid & 31;
    int wid  = tid >> 5;
    int wm   = wid >> 1;
    int wn   = wid & 1;
    int row0 = blockIdx.x * 128;

    int ar8   = tid >> 3;
    int ac8   = (tid & 7) * 4;
    int b_row = tid >> 2;
    int b_kc  = (tid & 3) * 8;

    float4 aS[4];
    uint4  bhS, blS;

    uint32_t a_ld_off = (uint32_t)((wm * 32 + (lane & 15)) * G2_STR + ((lane >> 4) << 3)) * 2;
    uint32_t b_ld_off = (uint32_t)((wn * 32 + (lane & 7) + ((lane >> 4) << 3)) * G2_STR
                                   + (((lane >> 3) & 1) << 3)) * 2;

    float acc[2][4][4];
    #pragma unroll
    for (int i = 0; i < 2; i++)
        #pragma unroll
        for (int j = 0; j < 4; j++)
            #pragma unroll
            for (int t = 0; t < 4; t++) acc[i][j][t] = 0.f;

    auto load_stage = [&](int kt) {
        #pragma unroll
        for (int p = 0; p < 4; p++) {
            int r = row0 + ar8 + p * 32;
            aS[p] = (r < NN)
                ? *reinterpret_cast<const float4*>(g_H1 + (size_t)r * HD + kt + ac8)
                : make_float4(0.f, 0.f, 0.f, 0.f);
        }
        bhS = *reinterpret_cast<const uint4*>(g_W1t_hi + (size_t)b_row * HD + kt + b_kc);
        blS = *reinterpret_cast<const uint4*>(g_W1t_lo + (size_t)b_row * HD + kt + b_kc);
    };

    auto store_stage = [&](int buf) {
        char* base = smem + buf * G2_BUF;
        #pragma unroll
        for (int p = 0; p < 4; p++) {
            float4 v = aS[p];
            __nv_bfloat162 h01 = __floats2bfloat162_rn(v.x, v.y);
            __nv_bfloat162 h23 = __floats2bfloat162_rn(v.z, v.w);
            float2 f01 = __bfloat1622float2(h01);
            float2 f23 = __bfloat1622float2(h23);
            __nv_bfloat162 l01 = __floats2bfloat162_rn(v.x - f01.x, v.y - f01.y);
            __nv_bfloat162 l23 = __floats2bfloat162_rn(v.z - f23.x, v.w - f23.y);
            uint32_t off = (uint32_t)((ar8 + p * 32) * G2_STR + ac8) * 2;
            *reinterpret_cast<uint2*>(base + G2_AH + off) =
                make_uint2(*(uint32_t*)&h01, *(uint32_t*)&h23);
            *reinterpret_cast<uint2*>(base + G2_AL + off) =
                make_uint2(*(uint32_t*)&l01, *(uint32_t*)&l23);
        }
        uint32_t boff = (uint32_t)(b_row * G2_STR + b_kc) * 2;
        *reinterpret_cast<uint4*>(base + G2_BH + boff) = bhS;
        *reinterpret_cast<uint4*>(base + G2_BL + boff) = blS;
    };

    auto compute = [&](int buf) {
        uint32_t ab = sb + buf * G2_BUF;
        #pragma unroll
        for (int ks = 0; ks < 2; ks++) {
            uint32_t kso = (uint32_t)(ks * 16) * 2;
            uint32_t ah[2][4], al[2][4], bh[4][2], bl[4][2];
            #pragma unroll
            for (int i = 0; i < 2; i++) {
                uint32_t ao = ab + a_ld_off + kso + (uint32_t)(i * 16 * G2_STR) * 2;
                ldmx4(ah[i], ao + G2_AH);
                ldmx4(al[i], ao + G2_AL);
            }
            #pragma unroll
            for (int j2 = 0; j2 < 2; j2++) {
                uint32_t bo = ab + b_ld_off + kso + (uint32_t)(j2 * 16 * G2_STR) * 2;
                uint32_t t[4];
                ldmx4(t, bo + G2_BH);
                bh[j2 * 2][0] = t[0]; bh[j2 * 2][1] = t[1];
                bh[j2 * 2 + 1][0] = t[2]; bh[j2 * 2 + 1][1] = t[3];
                ldmx4(t, bo + G2_BL);
                bl[j2 * 2][0] = t[0]; bl[j2 * 2][1] = t[1];
                bl[j2 * 2 + 1][0] = t[2]; bl[j2 * 2 + 1][1] = t[3];
            }
            #pragma unroll
            for (int i = 0; i < 2; i++)
                #pragma unroll
                for (int j = 0; j < 4; j++) {
                    mma16816b(acc[i][j], ah[i], bh[j][0], bh[j][1]);
                    mma16816b(acc[i][j], ah[i], bl[j][0], bl[j][1]);
                    mma16816b(acc[i][j], al[i], bh[j][0], bh[j][1]);
                }
        }
    };

    load_stage(0);
    store_stage(0);
    __syncthreads();

    for (int c = 0; c < G2_NC; c++) {
        if (c + 1 < G2_NC) load_stage((c + 1) * G2_KC);
        compute(c & 1);
        if (c + 1 < G2_NC) store_stage((c + 1) & 1);
        __syncthreads();
    }

    #pragma unroll
    for (int i = 0; i < 2; i++) {
        int r0 = row0 + wm * 32 + i * 16 + (lane >> 2);
        #pragma unroll
        for (int j = 0; j < 4; j++) {
            int cidx = wn * 32 + j * 8 + (lane & 3) * 2;
            if (r0 < NN)
                *reinterpret_cast<float2*>(g_H1W1 + (size_t)r0 * FD + cidx) =
                    make_float2(acc[i][j][0], acc[i][j][1]);
            if (r0 + 8 < NN)
                *reinterpret_cast<float2*>(g_H1W1 + (size_t)(r0 + 8) * FD + cidx) =
                    make_float2(acc[i][j][2], acc[i][j][3]);
        }
    }
}

// ---------------- SpMM2 + softmax, shfl-distributed edges -------------------------
__global__ void __launch_bounds__(256) spmm2_softmax_kernel(float* __restrict__ out) {
    int w    = (blockIdx.x * blockDim.x + threadIdx.x) >> 5;
    int lane = threadIdx.x & 31;
    if (w >= NN) return;

    int s = g_rowptr[w], e = g_rowptr[w + 1];
    const float2* Y2 = reinterpret_cast<const float2*>(g_H1W1);

    float ax = 0.f, ay = 0.f;
    int i = s;
    for (; i + 32 <= e; i += 32) {
        long long ev = *reinterpret_cast<const long long*>(&g_cedge[i + lane]);
        #pragma unroll
        for (int g = 0; g < 4; g++) {
            float v[8];
            float2 y[8];
            #pragma unroll
            for (int u = 0; u < 8; u++) {
                long long ed = __shfl_sync(0xffffffffu, ev, g * 8 + u);
                int col = (int)(ed & 0xffffffffll);
                v[u] = __int_as_float((int)(ed >> 32));
                y[u] = Y2[(size_t)col * 32 + lane];
            }
            #pragma unroll
            for (int u = 0; u < 8; u++) {
                ax = fmaf(v[u], y[u].x, ax);
                ay = fmaf(v[u], y[u].y, ay);
            }
        }
    }
    if (i < e) {
        int cnt = e - i;
        long long ev = 0;
        if (lane < cnt)
            ev = *reinterpret_cast<const long long*>(&g_cedge[i + lane]);
        for (int u = 0; u < cnt; u++) {
            long long ed = __shfl_sync(0xffffffffu, ev, u);
            int col = (int)(ed & 0xffffffffll);
            float v = __int_as_float((int)(ed >> 32));
            float2 y = Y2[(size_t)col * 32 + lane];
            ax = fmaf(v, y.x, ax);
            ay = fmaf(v, y.y, ay);
        }
    }

    float m = fmaxf(ax, ay);
    #pragma unroll
    for (int o = 16; o; o >>= 1) m = fmaxf(m, __shfl_xor_sync(0xffffffffu, m, o));
    float e0 = expf(ax - m), e1 = expf(ay - m);
    float sum = e0 + e1;
    #pragma unroll
    for (int o = 16; o; o >>= 1) sum += __shfl_xor_sync(0xffffffffu, sum, o);
    float inv = 1.f / sum;

    reinterpret_cast<float2*>(out)[(size_t)w * 32 + lane] = make_float2(e0 * inv, e1 * inv);
}

// ---------------- launcher ----------------------------------------------------------
extern "C" void kernel_launch(void* const* d_in, const int* in_sizes, int n_in,
                              void* d_out, int out_size) {
    const float* X  = (const float*)d_in[0];
    const int*   er = (const int*)d_in[1];
    const int*   ec = (const int*)d_in[2];
    const float* ev = (const float*)d_in[3];
    const float* W0 = (const float*)d_in[4];
    const float* W1 = (const float*)d_in[5];
    float* out = (float*)d_out;

    static cudaStream_t sB = nullptr;
    static cudaEvent_t evFork = nullptr, evCSR = nullptr;
    static bool init_done = false;
    if (!init_done) {
        cudaFuncSetAttribute(gemm1_mma_kernel,
                             cudaFuncAttributeMaxDynamicSharedMemorySize, G1_SMEM);
        cudaFuncSetAttribute(gemm2_mma_kernel,
                             cudaFuncAttributeMaxDynamicSharedMemorySize, G2_SMEM);
        cudaStreamCreateWithFlags(&sB, cudaStreamNonBlocking);
        cudaEventCreateWithFlags(&evFork, cudaEventDisableTiming);
        cudaEventCreateWithFlags(&evCSR, cudaEventDisableTiming);
        init_done = true;
    }

    // Fork: CSR build on side stream sB, concurrent with weight prep + GEMM1.
    cudaEventRecord(evFork, 0);
    cudaStreamWaitEvent(sB, evFork, 0);

    // --- branch B (sB): CSR build ---
    zero_cnt_kernel<<<(NN + 255) / 256, 256, 0, sB>>>();
    hist_kernel<<<(EE / 4 + 255) / 256, 256, 0, sB>>>((const int4*)er);
    scan_kernel<<<1, 1024, 0, sB>>>();
    scatter_kernel<<<(EE + 255) / 256, 256, 0, sB>>>(er, ec, ev);
    cudaEventRecord(evCSR, sB);

    // --- branch A (main): weight prep + GEMM1 ---
    w0_half_kernel<<<(K1 * HD + 255) / 256, 256>>>(W0);
    w1_split_kernel<<<(HD * FD + 255) / 256, 256>>>(W1);
    {
        dim3 grid((NN + 127) / 128, HD / 128);
        gemm1_mma_kernel<<<grid, 256, G1_SMEM>>>(X);
    }

    // Join: SpMM1 needs CSR + XW0h.
    cudaStreamWaitEvent(0, evCSR, 0);
    spmm1_relu_kernel<<<(NN * 32 + 255) / 256, 256>>>();

    // Layer 2 (sequential — overlap here was shown to be negative-sum).
    gemm2_mma_kernel<<<(NN + 127) / 128, 256, G2_SMEM>>>();
    spmm2_softmax_kernel<<<(NN * 32 + 255) / 256, 256>>>(out);
}

// round 15
// speedup vs baseline: 1.0375x; 1.0375x over previous
#include <cuda_runtime.h>
#include <cuda_bf16.h>
#include <cuda_fp16.h>
#include <cstdint>

#define NN 100000
#define EE 3200000
#define K1 512
#define HD 256
#define FD 64

// ---------------- scratch -----------------------------------------------------
__device__ __align__(16) __half g_XW0h[NN * HD];    // X @ W0 fp16 (51 MB)
__device__ __align__(16) float g_H1[NN * HD];       // relu(A @ XW0) fp32
__device__ __align__(16) float g_H1W1[NN * FD];     // logits precursor fp32
__device__ int   g_rowptr[NN + 1];
__device__ int   g_cursor[NN];
__device__ int   g_cnt[NN];
__device__ __align__(16) int2 g_cedge[EE];          // (col, valbits) fused
__device__ __align__(16) __half g_W0t_h[HD * K1];   // W0^T fp16 [256][512]
__device__ __align__(16) __nv_bfloat16 g_W1t_hi[FD * HD];  // W1^T split [64][256]
__device__ __align__(16) __nv_bfloat16 g_W1t_lo[FD * HD];

// ---------------- helpers ------------------------------------------------------
__device__ __forceinline__ uint32_t smem_u32(const void* p) {
    uint32_t a;
    asm("{ .reg .u64 t; cvta.to.shared.u64 t, %1; cvt.u32.u64 %0, t; }" : "=r"(a) : "l"(p));
    return a;
}
__device__ __forceinline__ void ldmx4(uint32_t* d, uint32_t addr) {
    asm volatile("ldmatrix.sync.aligned.m8n8.x4.shared.b16 {%0,%1,%2,%3}, [%4];"
                 : "=r"(d[0]), "=r"(d[1]), "=r"(d[2]), "=r"(d[3]) : "r"(addr));
}
__device__ __forceinline__ void mma16816h(float* c, const uint32_t* a, uint32_t b0, uint32_t b1) {
    asm volatile("mma.sync.aligned.m16n8k16.row.col.f32.f16.f16.f32 "
                 "{%0,%1,%2,%3}, {%4,%5,%6,%7}, {%8,%9}, {%0,%1,%2,%3};"
                 : "+f"(c[0]), "+f"(c[1]), "+f"(c[2]), "+f"(c[3])
                 : "r"(a[0]), "r"(a[1]), "r"(a[2]), "r"(a[3]), "r"(b0), "r"(b1));
}
__device__ __forceinline__ void mma16816b(float* c, const uint32_t* a, uint32_t b0, uint32_t b1) {
    asm volatile("mma.sync.aligned.m16n8k16.row.col.f32.bf16.bf16.f32 "
                 "{%0,%1,%2,%3}, {%4,%5,%6,%7}, {%8,%9}, {%0,%1,%2,%3};"
                 : "+f"(c[0]), "+f"(c[1]), "+f"(c[2]), "+f"(c[3])
                 : "r"(a[0]), "r"(a[1]), "r"(a[2]), "r"(a[3]), "r"(b0), "r"(b1));
}

// ---------------- CSR build -----------------------------------------------------
__global__ void zero_cnt_kernel() {
    int i = blockIdx.x * blockDim.x + threadIdx.x;
    if (i < NN) g_cnt[i] = 0;
}
__global__ void hist_kernel(const int4* __restrict__ rows4) {
    int i = blockIdx.x * blockDim.x + threadIdx.x;
    if (i < EE / 4) {
        int4 r = rows4[i];
        atomicAdd(&g_cnt[r.x], 1);
        atomicAdd(&g_cnt[r.y], 1);
        atomicAdd(&g_cnt[r.z], 1);
        atomicAdd(&g_cnt[r.w], 1);
    }
}
__global__ void __launch_bounds__(1024) scan_kernel() {
    __shared__ int wsum[32];
    int tid = threadIdx.x;
    const int PER = 98;
    int base = tid * PER;
    int s = 0;
    for (int j = 0; j < PER; j++) {
        int i = base + j;
        if (i < NN) s += g_cnt[i];
    }
    int lane = tid & 31, wid = tid >> 5;
    int x = s;
    #pragma unroll
    for (int o = 1; o < 32; o <<= 1) {
        int t = __shfl_up_sync(0xffffffffu, x, o);
        if (lane >= o) x += t;
    }
    if (lane == 31) wsum[wid] = x;
    __syncthreads();
    if (wid == 0) {
        int w = wsum[lane];
        #pragma unroll
        for (int o = 1; o < 32; o <<= 1) {
            int t = __shfl_up_sync(0xffffffffu, w, o);
            if (lane >= o) w += t;
        }
        wsum[lane] = w;
    }
    __syncthreads();
    int excl = x - s + (wid > 0 ? wsum[wid - 1] : 0);
    int run = excl;
    for (int j = 0; j < PER; j++) {
        int i = base + j;
        if (i < NN) {
            g_rowptr[i] = run;
            g_cursor[i] = run;
            run += g_cnt[i];
        }
    }
    if (tid == 1023) g_rowptr[NN] = run;
}
__global__ void scatter_kernel(const int* __restrict__ rows,
                               const int* __restrict__ cols,
                               const float* __restrict__ vals) {
    int i = blockIdx.x * blockDim.x + threadIdx.x;
    if (i < EE) {
        int r = rows[i];
        int p = atomicAdd(&g_cursor[r], 1);
        g_cedge[p] = make_int2(cols[i], __float_as_int(vals[i]));
    }
}

// ---------------- weight prep -----------------------------------------------------
__global__ void w0_half_kernel(const float* __restrict__ W0) {
    int i = blockIdx.x * blockDim.x + threadIdx.x;
    if (i < K1 * HD) {
        int k = i / HD, n = i % HD;
        g_W0t_h[n * K1 + k] = __float2half(W0[i]);
    }
}
__global__ void w1_split_kernel(const float* __restrict__ W1) {
    int i = blockIdx.x * blockDim.x + threadIdx.x;
    if (i < HD * FD) {
        int k = i / FD, n = i % FD;
        float v = W1[i];
        __nv_bfloat16 h = __float2bfloat16(v);
        g_W1t_hi[n * HD + k] = h;
        g_W1t_lo[n * HD + k] = __float2bfloat16(v - __bfloat162float(h));
    }
}

// ---------------- GEMM1 via mma.sync fp16, fp16 out ------------------------------
// Grid is (HD/128, row-tiles): the two col-half CTAs of each row-tile are adjacent
// in block order -> co-resident -> second CTA's X loads hit L2 (X read once from DRAM).
#define G1_KC   32
#define G1_NC   (K1 / G1_KC)
#define G1_STR  40
#define G1_BUF  20480                  // A 10240 | B 10240
#define G1_SMEM (2 * G1_BUF)

__global__ void __launch_bounds__(256, 2) gemm1_mma_kernel(const float* __restrict__ A) {
    extern __shared__ __align__(16) char smem[];
    uint32_t sb = smem_u32(smem);

    int tid  = threadIdx.x;
    int lane = tid & 31;
    int wid  = tid >> 5;
    int wm   = wid >> 2;
    int wn   = wid & 3;
    int row0 = blockIdx.y * 128;       // swapped: row tile on y
    int col0 = blockIdx.x * 128;       // col half on x (adjacent pairs)

    int a_row = tid >> 3;
    int a_kc  = (tid & 7) * 4;
    int b_row = tid >> 1;
    int b_kc  = (tid & 1) * 16;

    float4 aS[4];
    uint4  bS[2];

    uint32_t a_ld_off = (uint32_t)((wm * 64 + (lane & 15)) * G1_STR + ((lane >> 4) << 3)) * 2;
    uint32_t b_ld_off = (uint32_t)((wn * 32 + (lane & 7) + ((lane >> 4) << 3)) * G1_STR
                                   + (((lane >> 3) & 1) << 3)) * 2;

    float acc[4][4][4];
    #pragma unroll
    for (int i = 0; i < 4; i++)
        #pragma unroll
        for (int j = 0; j < 4; j++)
            #pragma unroll
            for (int t = 0; t < 4; t++) acc[i][j][t] = 0.f;

    auto load_stage = [&](int kt) {
        #pragma unroll
        for (int p = 0; p < 4; p++) {
            int r = row0 + a_row + p * 32;
            aS[p] = (r < NN)
                ? *reinterpret_cast<const float4*>(A + (size_t)r * K1 + kt + a_kc)
                : make_float4(0.f, 0.f, 0.f, 0.f);
        }
        int n = col0 + b_row;
        #pragma unroll
        for (int p = 0; p < 2; p++)
            bS[p] = *reinterpret_cast<const uint4*>(g_W0t_h + (size_t)n * K1 + kt + b_kc + p * 8);
    };

    auto store_stage = [&](int buf) {
        char* base = smem + buf * G1_BUF;
        #pragma unroll
        for (int p = 0; p < 4; p++) {
            float4 v = aS[p];
            __half2 h01 = __floats2half2_rn(v.x, v.y);
            __half2 h23 = __floats2half2_rn(v.z, v.w);
            uint32_t off = (uint32_t)((a_row + p * 32) * G1_STR + a_kc) * 2;
            *reinterpret_cast<uint2*>(base + off) =
                make_uint2(*(uint32_t*)&h01, *(uint32_t*)&h23);
        }
        #pragma unroll
        for (int p = 0; p < 2; p++) {
            uint32_t off = (uint32_t)(b_row * G1_STR + b_kc + p * 8) * 2;
            *reinterpret_cast<uint4*>(base + 10240 + off) = bS[p];
        }
    };

    auto compute = [&](int buf) {
        uint32_t ab = sb + buf * G1_BUF;
        #pragma unroll
        for (int ks = 0; ks < 2; ks++) {
            uint32_t kso = (uint32_t)(ks * 16) * 2;
            uint32_t ah[4][4], bh[4][2];
            #pragma unroll
            for (int i = 0; i < 4; i++) {
                uint32_t ao = ab + a_ld_off + kso + (uint32_t)(i * 16 * G1_STR) * 2;
                ldmx4(ah[i], ao);
            }
            #pragma unroll
            for (int j2 = 0; j2 < 2; j2++) {
                uint32_t bo = ab + 10240 + b_ld_off + kso + (uint32_t)(j2 * 16 * G1_STR) * 2;
                uint32_t t[4];
                ldmx4(t, bo);
                bh[j2 * 2][0] = t[0]; bh[j2 * 2][1] = t[1];
                bh[j2 * 2 + 1][0] = t[2]; bh[j2 * 2 + 1][1] = t[3];
            }
            #pragma unroll
            for (int i = 0; i < 4; i++)
                #pragma unroll
                for (int j = 0; j < 4; j++)
                    mma16816h(acc[i][j], ah[i], bh[j][0], bh[j][1]);
        }
    };

    load_stage(0);
    store_stage(0);
    __syncthreads();

    for (int c = 0; c < G1_NC; c++) {
        if (c + 1 < G1_NC) load_stage((c + 1) * G1_KC);
        compute(c & 1);
        if (c + 1 < G1_NC) store_stage((c + 1) & 1);
        __syncthreads();
    }

    #pragma unroll
    for (int i = 0; i < 4; i++) {
        int r0 = row0 + wm * 64 + i * 16 + (lane >> 2);
        #pragma unroll
        for (int j = 0; j < 4; j++) {
            int cidx = col0 + wn * 32 + j * 8 + (lane & 3) * 2;
            if (r0 < NN)
                *reinterpret_cast<__half2*>(g_XW0h + (size_t)r0 * HD + cidx) =
                    __floats2half2_rn(acc[i][j][0], acc[i][j][1]);
            if (r0 + 8 < NN)
                *reinterpret_cast<__half2*>(g_XW0h + (size_t)(r0 + 8) * HD + cidx) =
                    __floats2half2_rn(acc[i][j][2], acc[i][j][3]);
        }
    }
}

// ---------------- SpMM1: H1 = relu(A @ XW0h) -> fp32, warp per row ----------------
__device__ __forceinline__ void fmah8(float* acc, float v, const uint4& q) {
    const __half2* h = reinterpret_cast<const __half2*>(&q);
    #pragma unroll
    for (int t = 0; t < 4; t++) {
        float2 f = __half22float2(h[t]);
        acc[2 * t]     = fmaf(v, f.x, acc[2 * t]);
        acc[2 * t + 1] = fmaf(v, f.y, acc[2 * t + 1]);
    }
}

__global__ void __launch_bounds__(256) spmm1_relu_kernel() {
    int w    = (blockIdx.x * blockDim.x + threadIdx.x) >> 5;
    int lane = threadIdx.x & 31;
    if (w >= NN) return;

    int s = g_rowptr[w], e = g_rowptr[w + 1];
    const uint4* Yh = reinterpret_cast<const uint4*>(g_XW0h);

    float acc[8];
    #pragma unroll
    for (int t = 0; t < 8; t++) acc[t] = 0.f;

    int i = s;
    for (; i + 8 <= e; i += 8) {
        int2 ed[8];
        uint4 q[8];
        #pragma unroll
        for (int u = 0; u < 8; u++) ed[u] = g_cedge[i + u];
        #pragma unroll
        for (int u = 0; u < 8; u++) q[u] = Yh[(size_t)ed[u].x * 32 + lane];
        #pragma unroll
        for (int u = 0; u < 8; u++) fmah8(acc, __int_as_float(ed[u].y), q[u]);
    }
    for (; i + 4 <= e; i += 4) {
        int2 e0 = g_cedge[i],     e1 = g_cedge[i + 1];
        int2 e2 = g_cedge[i + 2], e3 = g_cedge[i + 3];
        uint4 q0 = Yh[(size_t)e0.x * 32 + lane];
        uint4 q1 = Yh[(size_t)e1.x * 32 + lane];
        uint4 q2 = Yh[(size_t)e2.x * 32 + lane];
        uint4 q3 = Yh[(size_t)e3.x * 32 + lane];
        fmah8(acc, __int_as_float(e0.y), q0);
        fmah8(acc, __int_as_float(e1.y), q1);
        fmah8(acc, __int_as_float(e2.y), q2);
        fmah8(acc, __int_as_float(e3.y), q3);
    }
    for (; i < e; i++) {
        int2 ed = g_cedge[i];
        uint4 q = Yh[(size_t)ed.x * 32 + lane];
        fmah8(acc, __int_as_float(ed.y), q);
    }

    float* dst = g_H1 + (size_t)w * HD + lane * 8;
    *reinterpret_cast<float4*>(dst) =
        make_float4(fmaxf(acc[0], 0.f), fmaxf(acc[1], 0.f),
                    fmaxf(acc[2], 0.f), fmaxf(acc[3], 0.f));
    *reinterpret_cast<float4*>(dst + 4) =
        make_float4(fmaxf(acc[4], 0.f), fmaxf(acc[5], 0.f),
                    fmaxf(acc[6], 0.f), fmaxf(acc[7], 0.f));
}

// ---------------- GEMM2 via mma.sync split-bf16 (3 products): fp32 in/out ---------
#define G2_KC   32
#define G2_NC   (HD / G2_KC)          // 8
#define G2_STR  40
#define G2_AH   0
#define G2_AL   10240
#define G2_BH   20480
#define G2_BL   25600
#define G2_BUF  30720
#define G2_SMEM (2 * G2_BUF)

__global__ void __launch_bounds__(256) gemm2_mma_kernel() {
    extern __shared__ __align__(16) char smem[];
    uint32_t sb = smem_u32(smem);

    int tid  = threadIdx.x;
    int lane = tid & 31;
    int wid  = tid >> 5;
    int wm   = wid >> 1;
    int wn   = wid & 1;
    int row0 = blockIdx.x * 128;

    int ar8   = tid >> 3;
    int ac8   = (tid & 7) * 4;
    int b_row = tid >> 2;
    int b_kc  = (tid & 3) * 8;

    float4 aS[4];
    uint4  bhS, blS;

    uint32_t a_ld_off = (uint32_t)((wm * 32 + (lane & 15)) * G2_STR + ((lane >> 4) << 3)) * 2;
    uint32_t b_ld_off = (uint32_t)((wn * 32 + (lane & 7) + ((lane >> 4) << 3)) * G2_STR
                                   + (((lane >> 3) & 1) << 3)) * 2;

    float acc[2][4][4];
    #pragma unroll
    for (int i = 0; i < 2; i++)
        #pragma unroll
        for (int j = 0; j < 4; j++)
            #pragma unroll
            for (int t = 0; t < 4; t++) acc[i][j][t] = 0.f;

    auto load_stage = [&](int kt) {
        #pragma unroll
        for (int p = 0; p < 4; p++) {
            int r = row0 + ar8 + p * 32;
            aS[p] = (r < NN)
                ? *reinterpret_cast<const float4*>(g_H1 + (size_t)r * HD + kt + ac8)
                : make_float4(0.f, 0.f, 0.f, 0.f);
        }
        bhS = *reinterpret_cast<const uint4*>(g_W1t_hi + (size_t)b_row * HD + kt + b_kc);
        blS = *reinterpret_cast<const uint4*>(g_W1t_lo + (size_t)b_row * HD + kt + b_kc);
    };

    auto store_stage = [&](int buf) {
        char* base = smem + buf * G2_BUF;
        #pragma unroll
        for (int p = 0; p < 4; p++) {
            float4 v = aS[p];
            __nv_bfloat162 h01 = __floats2bfloat162_rn(v.x, v.y);
            __nv_bfloat162 h23 = __floats2bfloat162_rn(v.z, v.w);
            float2 f01 = __bfloat1622float2(h01);
            float2 f23 = __bfloat1622float2(h23);
            __nv_bfloat162 l01 = __floats2bfloat162_rn(v.x - f01.x, v.y - f01.y);
            __nv_bfloat162 l23 = __floats2bfloat162_rn(v.z - f23.x, v.w - f23.y);
            uint32_t off = (uint32_t)((ar8 + p * 32) * G2_STR + ac8) * 2;
            *reinterpret_cast<uint2*>(base + G2_AH + off) =
                make_uint2(*(uint32_t*)&h01, *(uint32_t*)&h23);
            *reinterpret_cast<uint2*>(base + G2_AL + off) =
                make_uint2(*(uint32_t*)&l01, *(uint32_t*)&l23);
        }
        uint32_t boff = (uint32_t)(b_row * G2_STR + b_kc) * 2;
        *reinterpret_cast<uint4*>(base + G2_BH + boff) = bhS;
        *reinterpret_cast<uint4*>(base + G2_BL + boff) = blS;
    };

    auto compute = [&](int buf) {
        uint32_t ab = sb + buf * G2_BUF;
        #pragma unroll
        for (int ks = 0; ks < 2; ks++) {
            uint32_t kso = (uint32_t)(ks * 16) * 2;
            uint32_t ah[2][4], al[2][4], bh[4][2], bl[4][2];
            #pragma unroll
            for (int i = 0; i < 2; i++) {
                uint32_t ao = ab + a_ld_off + kso + (uint32_t)(i * 16 * G2_STR) * 2;
                ldmx4(ah[i], ao + G2_AH);
                ldmx4(al[i], ao + G2_AL);
            }
            #pragma unroll
            for (int j2 = 0; j2 < 2; j2++) {
                uint32_t bo = ab + b_ld_off + kso + (uint32_t)(j2 * 16 * G2_STR) * 2;
                uint32_t t[4];
                ldmx4(t, bo + G2_BH);
                bh[j2 * 2][0] = t[0]; bh[j2 * 2][1] = t[1];
                bh[j2 * 2 + 1][0] = t[2]; bh[j2 * 2 + 1][1] = t[3];
                ldmx4(t, bo + G2_BL);
                bl[j2 * 2][0] = t[0]; bl[j2 * 2][1] = t[1];
                bl[j2 * 2 + 1][0] = t[2]; bl[j2 * 2 + 1][1] = t[3];
            }
            #pragma unroll
            for (int i = 0; i < 2; i++)
                #pragma unroll
                for (int j = 0; j < 4; j++) {
                    mma16816b(acc[i][j], ah[i], bh[j][0], bh[j][1]);
                    mma16816b(acc[i][j], ah[i], bl[j][0], bl[j][1]);
                    mma16816b(acc[i][j], al[i], bh[j][0], bh[j][1]);
                }
        }
    };

    load_stage(0);
    store_stage(0);
    __syncthreads();

    for (int c = 0; c < G2_NC; c++) {
        if (c + 1 < G2_NC) load_stage((c + 1) * G2_KC);
        compute(c & 1);
        if (c + 1 < G2_NC) store_stage((c + 1) & 1);
        __syncthreads();
    }

    #pragma unroll
    for (int i = 0; i < 2; i++) {
        int r0 = row0 + wm * 32 + i * 16 + (lane >> 2);
        #pragma unroll
        for (int j = 0; j < 4; j++) {
            int cidx = wn * 32 + j * 8 + (lane & 3) * 2;
            if (r0 < NN)
                *reinterpret_cast<float2*>(g_H1W1 + (size_t)r0 * FD + cidx) =
                    make_float2(acc[i][j][0], acc[i][j][1]);
            if (r0 + 8 < NN)
                *reinterpret_cast<float2*>(g_H1W1 + (size_t)(r0 + 8) * FD + cidx) =
                    make_float2(acc[i][j][2], acc[i][j][3]);
        }
    }
}

// ---------------- SpMM2 + softmax (fp32 gather) -----------------------------------
__global__ void __launch_bounds__(256) spmm2_softmax_kernel(float* __restrict__ out) {
    int w    = (blockIdx.x * blockDim.x + threadIdx.x) >> 5;
    int lane = threadIdx.x & 31;
    if (w >= NN) return;

    int s = g_rowptr[w], e = g_rowptr[w + 1];
    const float2* Y2 = reinterpret_cast<const float2*>(g_H1W1);

    float ax = 0.f, ay = 0.f;
    int i = s;
    for (; i + 4 <= e; i += 4) {
        int2 e0 = g_cedge[i],     e1 = g_cedge[i + 1];
        int2 e2 = g_cedge[i + 2], e3 = g_cedge[i + 3];
        float2 y0 = Y2[(size_t)e0.x * 32 + lane];
        float2 y1 = Y2[(size_t)e1.x * 32 + lane];
        float2 y2 = Y2[(size_t)e2.x * 32 + lane];
        float2 y3 = Y2[(size_t)e3.x * 32 + lane];
        float v0 = __int_as_float(e0.y), v1 = __int_as_float(e1.y);
        float v2 = __int_as_float(e2.y), v3 = __int_as_float(e3.y);
        ax = fmaf(v0, y0.x, ax); ay = fmaf(v0, y0.y, ay);
        ax = fmaf(v1, y1.x, ax); ay = fmaf(v1, y1.y, ay);
        ax = fmaf(v2, y2.x, ax); ay = fmaf(v2, y2.y, ay);
        ax = fmaf(v3, y3.x, ax); ay = fmaf(v3, y3.y, ay);
    }
    for (; i < e; i++) {
        int2 ed = g_cedge[i];
        float v = __int_as_float(ed.y);
        float2 y = Y2[(size_t)ed.x * 32 + lane];
        ax = fmaf(v, y.x, ax); ay = fmaf(v, y.y, ay);
    }

    float m = fmaxf(ax, ay);
    #pragma unroll
    for (int o = 16; o; o >>= 1) m = fmaxf(m, __shfl_xor_sync(0xffffffffu, m, o));
    float e0 = expf(ax - m), e1 = expf(ay - m);
    float sum = e0 + e1;
    #pragma unroll
    for (int o = 16; o; o >>= 1) sum += __shfl_xor_sync(0xffffffffu, sum, o);
    float inv = 1.f / sum;

    reinterpret_cast<float2*>(out)[(size_t)w * 32 + lane] = make_float2(e0 * inv, e1 * inv);
}

// ---------------- launcher ----------------------------------------------------------
extern "C" void kernel_launch(void* const* d_in, const int* in_sizes, int n_in,
                              void* d_out, int out_size) {
    const float* X  = (const float*)d_in[0];
    const int*   er = (const int*)d_in[1];
    const int*   ec = (const int*)d_in[2];
    const float* ev = (const float*)d_in[3];
    const float* W0 = (const float*)d_in[4];
    const float* W1 = (const float*)d_in[5];
    float* out = (float*)d_out;

    static cudaStream_t sB = nullptr;
    static cudaEvent_t evFork = nullptr, evCSR = nullptr;
    static bool init_done = false;
    if (!init_done) {
        cudaFuncSetAttribute(gemm1_mma_kernel,
                             cudaFuncAttributeMaxDynamicSharedMemorySize, G1_SMEM);
        cudaFuncSetAttribute(gemm2_mma_kernel,
                             cudaFuncAttributeMaxDynamicSharedMemorySize, G2_SMEM);
        cudaStreamCreateWithFlags(&sB, cudaStreamNonBlocking);
        cudaEventCreateWithFlags(&evFork, cudaEventDisableTiming);
        cudaEventCreateWithFlags(&evCSR, cudaEventDisableTiming);
        init_done = true;
    }

    // Fork: CSR build on side stream sB, concurrent with weight prep + GEMM1.
    cudaEventRecord(evFork, 0);
    cudaStreamWaitEvent(sB, evFork, 0);

    // --- branch B (sB): CSR build ---
    zero_cnt_kernel<<<(NN + 255) / 256, 256, 0, sB>>>();
    hist_kernel<<<(EE / 4 + 255) / 256, 256, 0, sB>>>((const int4*)er);
    scan_kernel<<<1, 1024, 0, sB>>>();
    scatter_kernel<<<(EE + 255) / 256, 256, 0, sB>>>(er, ec, ev);
    cudaEventRecord(evCSR, sB);

    // --- branch A (main): weight prep + GEMM1 ---
    w0_half_kernel<<<(K1 * HD + 255) / 256, 256>>>(W0);
    w1_split_kernel<<<(HD * FD + 255) / 256, 256>>>(W1);
    {
        // col halves on x (adjacent -> co-resident -> X L2 reuse), row tiles on y
        dim3 grid(HD / 128, (NN + 127) / 128);
        gemm1_mma_kernel<<<grid, 256, G1_SMEM>>>(X);
    }

    // Join: SpMM1 needs CSR + XW0h.
    cudaStreamWaitEvent(0, evCSR, 0);
    spmm1_relu_kernel<<<(NN * 32 + 255) / 256, 256>>>();

    // Layer 2 (sequential — overlap here was shown to be negative-sum).
    gemm2_mma_kernel<<<(NN + 127) / 128, 256, G2_SMEM>>>();
    spmm2_softmax_kernel<<<(NN * 32 + 255) / 256, 256>>>(out);
}

// round 16
// speedup vs baseline: 1.0573x; 1.0191x over previous
#include <cuda_runtime.h>
#include <cuda_bf16.h>
#include <cuda_fp16.h>
#include <cstdint>

#define NN 100000
#define EE 3200000
#define K1 512
#define HD 256
#define FD 64

// ---------------- scratch -----------------------------------------------------
__device__ __align__(16) __half g_XW0h[NN * HD];    // X @ W0 fp16 (51 MB)
__device__ __align__(16) float g_H1[NN * HD];       // relu(A @ XW0) fp32
__device__ __align__(16) float g_H1W1[NN * FD];     // logits precursor fp32
__device__ int   g_rowptr[NN + 1];
__device__ int   g_cursor[NN];
__device__ int   g_cnt[NN];
__device__ __align__(16) int2 g_cedge[EE];          // (col, valbits) fused
__device__ __align__(16) __half g_W0t_h[HD * K1];   // W0^T fp16 [256][512]
__device__ __align__(16) __nv_bfloat16 g_W1t_hi[FD * HD];  // W1^T split [64][256]
__device__ __align__(16) __nv_bfloat16 g_W1t_lo[FD * HD];

// ---------------- helpers ------------------------------------------------------
__device__ __forceinline__ uint32_t smem_u32(const void* p) {
    uint32_t a;
    asm("{ .reg .u64 t; cvta.to.shared.u64 t, %1; cvt.u32.u64 %0, t; }" : "=r"(a) : "l"(p));
    return a;
}
__device__ __forceinline__ void ldmx4(uint32_t* d, uint32_t addr) {
    asm volatile("ldmatrix.sync.aligned.m8n8.x4.shared.b16 {%0,%1,%2,%3}, [%4];"
                 : "=r"(d[0]), "=r"(d[1]), "=r"(d[2]), "=r"(d[3]) : "r"(addr));
}
__device__ __forceinline__ void mma16816h(float* c, const uint32_t* a, uint32_t b0, uint32_t b1) {
    asm volatile("mma.sync.aligned.m16n8k16.row.col.f32.f16.f16.f32 "
                 "{%0,%1,%2,%3}, {%4,%5,%6,%7}, {%8,%9}, {%0,%1,%2,%3};"
                 : "+f"(c[0]), "+f"(c[1]), "+f"(c[2]), "+f"(c[3])
                 : "r"(a[0]), "r"(a[1]), "r"(a[2]), "r"(a[3]), "r"(b0), "r"(b1));
}
__device__ __forceinline__ void mma16816b(float* c, const uint32_t* a, uint32_t b0, uint32_t b1) {
    asm volatile("mma.sync.aligned.m16n8k16.row.col.f32.bf16.bf16.f32 "
                 "{%0,%1,%2,%3}, {%4,%5,%6,%7}, {%8,%9}, {%0,%1,%2,%3};"
                 : "+f"(c[0]), "+f"(c[1]), "+f"(c[2]), "+f"(c[3])
                 : "r"(a[0]), "r"(a[1]), "r"(a[2]), "r"(a[3]), "r"(b0), "r"(b1));
}

// ---------------- CSR build -----------------------------------------------------
__global__ void zero_cnt_kernel() {
    int i = blockIdx.x * blockDim.x + threadIdx.x;
    if (i < NN) g_cnt[i] = 0;
}
__global__ void hist_kernel(const int4* __restrict__ rows4) {
    int i = blockIdx.x * blockDim.x + threadIdx.x;
    if (i < EE / 4) {
        int4 r = rows4[i];
        atomicAdd(&g_cnt[r.x], 1);
        atomicAdd(&g_cnt[r.y], 1);
        atomicAdd(&g_cnt[r.z], 1);
        atomicAdd(&g_cnt[r.w], 1);
    }
}
__global__ void __launch_bounds__(1024) scan_kernel() {
    __shared__ int wsum[32];
    int tid = threadIdx.x;
    const int PER = 98;
    int base = tid * PER;
    int s = 0;
    for (int j = 0; j < PER; j++) {
        int i = base + j;
        if (i < NN) s += g_cnt[i];
    }
    int lane = tid & 31, wid = tid >> 5;
    int x = s;
    #pragma unroll
    for (int o = 1; o < 32; o <<= 1) {
        int t = __shfl_up_sync(0xffffffffu, x, o);
        if (lane >= o) x += t;
    }
    if (lane == 31) wsum[wid] = x;
    __syncthreads();
    if (wid == 0) {
        int w = wsum[lane];
        #pragma unroll
        for (int o = 1; o < 32; o <<= 1) {
            int t = __shfl_up_sync(0xffffffffu, w, o);
            if (lane >= o) w += t;
        }
        wsum[lane] = w;
    }
    __syncthreads();
    int excl = x - s + (wid > 0 ? wsum[wid - 1] : 0);
    int run = excl;
    for (int j = 0; j < PER; j++) {
        int i = base + j;
        if (i < NN) {
            g_rowptr[i] = run;
            g_cursor[i] = run;
            run += g_cnt[i];
        }
    }
    if (tid == 1023) g_rowptr[NN] = run;
}
__global__ void scatter_kernel(const int* __restrict__ rows,
                               const int* __restrict__ cols,
                               const float* __restrict__ vals) {
    int i = blockIdx.x * blockDim.x + threadIdx.x;
    if (i < EE) {
        int r = rows[i];
        int p = atomicAdd(&g_cursor[r], 1);
        g_cedge[p] = make_int2(cols[i], __float_as_int(vals[i]));
    }
}

// ---------------- weight prep (merged) --------------------------------------------
__global__ void wprep_kernel(const float* __restrict__ W0, const float* __restrict__ W1) {
    int i = blockIdx.x * blockDim.x + threadIdx.x;
    if (i < K1 * HD) {
        int k = i / HD, n = i % HD;
        g_W0t_h[n * K1 + k] = __float2half(W0[i]);
    } else {
        int j = i - K1 * HD;
        if (j < HD * FD) {
            int k = j / FD, n = j % FD;
            float v = W1[j];
            __nv_bfloat16 h = __float2bfloat16(v);
            g_W1t_hi[n * HD + k] = h;
            g_W1t_lo[n * HD + k] = __float2bfloat16(v - __bfloat162float(h));
        }
    }
}

// ---------------- GEMM1 via mma.sync fp16, fp16 out ------------------------------
#define G1_KC   32
#define G1_NC   (K1 / G1_KC)
#define G1_STR  40
#define G1_BUF  20480                  // A 10240 | B 10240
#define G1_SMEM (2 * G1_BUF)

__global__ void __launch_bounds__(256, 2) gemm1_mma_kernel(const float* __restrict__ A) {
    extern __shared__ __align__(16) char smem[];
    uint32_t sb = smem_u32(smem);

    int tid  = threadIdx.x;
    int lane = tid & 31;
    int wid  = tid >> 5;
    int wm   = wid >> 2;
    int wn   = wid & 3;
    int row0 = blockIdx.y * 128;
    int col0 = blockIdx.x * 128;

    int a_row = tid >> 3;
    int a_kc  = (tid & 7) * 4;
    int b_row = tid >> 1;
    int b_kc  = (tid & 1) * 16;

    float4 aS[4];
    uint4  bS[2];

    uint32_t a_ld_off = (uint32_t)((wm * 64 + (lane & 15)) * G1_STR + ((lane >> 4) << 3)) * 2;
    uint32_t b_ld_off = (uint32_t)((wn * 32 + (lane & 7) + ((lane >> 4) << 3)) * G1_STR
                                   + (((lane >> 3) & 1) << 3)) * 2;

    float acc[4][4][4];
    #pragma unroll
    for (int i = 0; i < 4; i++)
        #pragma unroll
        for (int j = 0; j < 4; j++)
            #pragma unroll
            for (int t = 0; t < 4; t++) acc[i][j][t] = 0.f;

    auto load_stage = [&](int kt) {
        #pragma unroll
        for (int p = 0; p < 4; p++) {
            int r = row0 + a_row + p * 32;
            aS[p] = (r < NN)
                ? *reinterpret_cast<const float4*>(A + (size_t)r * K1 + kt + a_kc)
                : make_float4(0.f, 0.f, 0.f, 0.f);
        }
        int n = col0 + b_row;
        #pragma unroll
        for (int p = 0; p < 2; p++)
            bS[p] = *reinterpret_cast<const uint4*>(g_W0t_h + (size_t)n * K1 + kt + b_kc + p * 8);
    };

    auto store_stage = [&](int buf) {
        char* base = smem + buf * G1_BUF;
        #pragma unroll
        for (int p = 0; p < 4; p++) {
            float4 v = aS[p];
            __half2 h01 = __floats2half2_rn(v.x, v.y);
            __half2 h23 = __floats2half2_rn(v.z, v.w);
            uint32_t off = (uint32_t)((a_row + p * 32) * G1_STR + a_kc) * 2;
            *reinterpret_cast<uint2*>(base + off) =
                make_uint2(*(uint32_t*)&h01, *(uint32_t*)&h23);
        }
        #pragma unroll
        for (int p = 0; p < 2; p++) {
            uint32_t off = (uint32_t)(b_row * G1_STR + b_kc + p * 8) * 2;
            *reinterpret_cast<uint4*>(base + 10240 + off) = bS[p];
        }
    };

    auto compute = [&](int buf) {
        uint32_t ab = sb + buf * G1_BUF;
        #pragma unroll
        for (int ks = 0; ks < 2; ks++) {
            uint32_t kso = (uint32_t)(ks * 16) * 2;
            uint32_t ah[4][4], bh[4][2];
            #pragma unroll
            for (int i = 0; i < 4; i++) {
                uint32_t ao = ab + a_ld_off + kso + (uint32_t)(i * 16 * G1_STR) * 2;
                ldmx4(ah[i], ao);
            }
            #pragma unroll
            for (int j2 = 0; j2 < 2; j2++) {
                uint32_t bo = ab + 10240 + b_ld_off + kso + (uint32_t)(j2 * 16 * G1_STR) * 2;
                uint32_t t[4];
                ldmx4(t, bo);
                bh[j2 * 2][0] = t[0]; bh[j2 * 2][1] = t[1];
                bh[j2 * 2 + 1][0] = t[2]; bh[j2 * 2 + 1][1] = t[3];
            }
            #pragma unroll
            for (int i = 0; i < 4; i++)
                #pragma unroll
                for (int j = 0; j < 4; j++)
                    mma16816h(acc[i][j], ah[i], bh[j][0], bh[j][1]);
        }
    };

    load_stage(0);
    store_stage(0);
    __syncthreads();

    for (int c = 0; c < G1_NC; c++) {
        if (c + 1 < G1_NC) load_stage((c + 1) * G1_KC);
        compute(c & 1);
        if (c + 1 < G1_NC) store_stage((c + 1) & 1);
        __syncthreads();
    }

    #pragma unroll
    for (int i = 0; i < 4; i++) {
        int r0 = row0 + wm * 64 + i * 16 + (lane >> 2);
        #pragma unroll
        for (int j = 0; j < 4; j++) {
            int cidx = col0 + wn * 32 + j * 8 + (lane & 3) * 2;
            if (r0 < NN)
                *reinterpret_cast<__half2*>(g_XW0h + (size_t)r0 * HD + cidx) =
                    __floats2half2_rn(acc[i][j][0], acc[i][j][1]);
            if (r0 + 8 < NN)
                *reinterpret_cast<__half2*>(g_XW0h + (size_t)(r0 + 8) * HD + cidx) =
                    __floats2half2_rn(acc[i][j][2], acc[i][j][3]);
        }
    }
}

// ---------------- SpMM1: H1 = relu(A @ XW0h) -> fp32, warp per row ----------------
__device__ __forceinline__ void fmah8(float* acc, float v, const uint4& q) {
    const __half2* h = reinterpret_cast<const __half2*>(&q);
    #pragma unroll
    for (int t = 0; t < 4; t++) {
        float2 f = __half22float2(h[t]);
        acc[2 * t]     = fmaf(v, f.x, acc[2 * t]);
        acc[2 * t + 1] = fmaf(v, f.y, acc[2 * t + 1]);
    }
}

__global__ void __launch_bounds__(256) spmm1_relu_kernel() {
    int w    = (blockIdx.x * blockDim.x + threadIdx.x) >> 5;
    int lane = threadIdx.x & 31;
    if (w >= NN) return;

    int s = g_rowptr[w], e = g_rowptr[w + 1];
    const uint4* Yh = reinterpret_cast<const uint4*>(g_XW0h);

    float acc[8];
    #pragma unroll
    for (int t = 0; t < 8; t++) acc[t] = 0.f;

    int i = s;
    for (; i + 8 <= e; i += 8) {
        int2 ed[8];
        uint4 q[8];
        #pragma unroll
        for (int u = 0; u < 8; u++) ed[u] = g_cedge[i + u];
        #pragma unroll
        for (int u = 0; u < 8; u++) q[u] = Yh[(size_t)ed[u].x * 32 + lane];
        #pragma unroll
        for (int u = 0; u < 8; u++) fmah8(acc, __int_as_float(ed[u].y), q[u]);
    }
    for (; i + 4 <= e; i += 4) {
        int2 e0 = g_cedge[i],     e1 = g_cedge[i + 1];
        int2 e2 = g_cedge[i + 2], e3 = g_cedge[i + 3];
        uint4 q0 = Yh[(size_t)e0.x * 32 + lane];
        uint4 q1 = Yh[(size_t)e1.x * 32 + lane];
        uint4 q2 = Yh[(size_t)e2.x * 32 + lane];
        uint4 q3 = Yh[(size_t)e3.x * 32 + lane];
        fmah8(acc, __int_as_float(e0.y), q0);
        fmah8(acc, __int_as_float(e1.y), q1);
        fmah8(acc, __int_as_float(e2.y), q2);
        fmah8(acc, __int_as_float(e3.y), q3);
    }
    for (; i < e; i++) {
        int2 ed = g_cedge[i];
        uint4 q = Yh[(size_t)ed.x * 32 + lane];
        fmah8(acc, __int_as_float(ed.y), q);
    }

    float* dst = g_H1 + (size_t)w * HD + lane * 8;
    *reinterpret_cast<float4*>(dst) =
        make_float4(fmaxf(acc[0], 0.f), fmaxf(acc[1], 0.f),
                    fmaxf(acc[2], 0.f), fmaxf(acc[3], 0.f));
    *reinterpret_cast<float4*>(dst + 4) =
        make_float4(fmaxf(acc[4], 0.f), fmaxf(acc[5], 0.f),
                    fmaxf(acc[6], 0.f), fmaxf(acc[7], 0.f));
}

// ---------------- GEMM2 via mma.sync split-bf16 (3 products): fp32 in/out ---------
#define G2_KC   32
#define G2_NC   (HD / G2_KC)          // 8
#define G2_STR  40
#define G2_AH   0
#define G2_AL   10240
#define G2_BH   20480
#define G2_BL   25600
#define G2_BUF  30720
#define G2_SMEM (2 * G2_BUF)

__global__ void __launch_bounds__(256) gemm2_mma_kernel() {
    extern __shared__ __align__(16) char smem[];
    uint32_t sb = smem_u32(smem);

    int tid  = threadIdx.x;
    int lane = tid & 31;
    int wid  = tid >> 5;
    int wm   = wid >> 1;
    int wn   = wid & 1;
    int row0 = blockIdx.x * 128;

    int ar8   = tid >> 3;
    int ac8   = (tid & 7) * 4;
    int b_row = tid >> 2;
    int b_kc  = (tid & 3) * 8;

    float4 aS[4];
    uint4  bhS, blS;

    uint32_t a_ld_off = (uint32_t)((wm * 32 + (lane & 15)) * G2_STR + ((lane >> 4) << 3)) * 2;
    uint32_t b_ld_off = (uint32_t)((wn * 32 + (lane & 7) + ((lane >> 4) << 3)) * G2_STR
                                   + (((lane >> 3) & 1) << 3)) * 2;

    float acc[2][4][4];
    #pragma unroll
    for (int i = 0; i < 2; i++)
        #pragma unroll
        for (int j = 0; j < 4; j++)
            #pragma unroll
            for (int t = 0; t < 4; t++) acc[i][j][t] = 0.f;

    auto load_stage = [&](int kt) {
        #pragma unroll
        for (int p = 0; p < 4; p++) {
            int r = row0 + ar8 + p * 32;
            aS[p] = (r < NN)
                ? *reinterpret_cast<const float4*>(g_H1 + (size_t)r * HD + kt + ac8)
                : make_float4(0.f, 0.f, 0.f, 0.f);
        }
        bhS = *reinterpret_cast<const uint4*>(g_W1t_hi + (size_t)b_row * HD + kt + b_kc);
        blS = *reinterpret_cast<const uint4*>(g_W1t_lo + (size_t)b_row * HD + kt + b_kc);
    };

    auto store_stage = [&](int buf) {
        char* base = smem + buf * G2_BUF;
        #pragma unroll
        for (int p = 0; p < 4; p++) {
            float4 v = aS[p];
            __nv_bfloat162 h01 = __floats2bfloat162_rn(v.x, v.y);
            __nv_bfloat162 h23 = __floats2bfloat162_rn(v.z, v.w);
            float2 f01 = __bfloat1622float2(h01);
            float2 f23 = __bfloat1622float2(h23);
            __nv_bfloat162 l01 = __floats2bfloat162_rn(v.x - f01.x, v.y - f01.y);
            __nv_bfloat162 l23 = __floats2bfloat162_rn(v.z - f23.x, v.w - f23.y);
            uint32_t off = (uint32_t)((ar8 + p * 32) * G2_STR + ac8) * 2;
            *reinterpret_cast<uint2*>(base + G2_AH + off) =
                make_uint2(*(uint32_t*)&h01, *(uint32_t*)&h23);
            *reinterpret_cast<uint2*>(base + G2_AL + off) =
                make_uint2(*(uint32_t*)&l01, *(uint32_t*)&l23);
        }
        uint32_t boff = (uint32_t)(b_row * G2_STR + b_kc) * 2;
        *reinterpret_cast<uint4*>(base + G2_BH + boff) = bhS;
        *reinterpret_cast<uint4*>(base + G2_BL + boff) = blS;
    };

    auto compute = [&](int buf) {
        uint32_t ab = sb + buf * G2_BUF;
        #pragma unroll
        for (int ks = 0; ks < 2; ks++) {
            uint32_t kso = (uint32_t)(ks * 16) * 2;
            uint32_t ah[2][4], al[2][4], bh[4][2], bl[4][2];
            #pragma unroll
            for (int i = 0; i < 2; i++) {
                uint32_t ao = ab + a_ld_off + kso + (uint32_t)(i * 16 * G2_STR) * 2;
                ldmx4(ah[i], ao + G2_AH);
                ldmx4(al[i], ao + G2_AL);
            }
            #pragma unroll
            for (int j2 = 0; j2 < 2; j2++) {
                uint32_t bo = ab + b_ld_off + kso + (uint32_t)(j2 * 16 * G2_STR) * 2;
                uint32_t t[4];
                ldmx4(t, bo + G2_BH);
                bh[j2 * 2][0] = t[0]; bh[j2 * 2][1] = t[1];
                bh[j2 * 2 + 1][0] = t[2]; bh[j2 * 2 + 1][1] = t[3];
                ldmx4(t, bo + G2_BL);
                bl[j2 * 2][0] = t[0]; bl[j2 * 2][1] = t[1];
                bl[j2 * 2 + 1][0] = t[2]; bl[j2 * 2 + 1][1] = t[3];
            }
            #pragma unroll
            for (int i = 0; i < 2; i++)
                #pragma unroll
                for (int j = 0; j < 4; j++) {
                    mma16816b(acc[i][j], ah[i], bh[j][0], bh[j][1]);
                    mma16816b(acc[i][j], ah[i], bl[j][0], bl[j][1]);
                    mma16816b(acc[i][j], al[i], bh[j][0], bh[j][1]);
                }
        }
    };

    load_stage(0);
    store_stage(0);
    __syncthreads();

    for (int c = 0; c < G2_NC; c++) {
        if (c + 1 < G2_NC) load_stage((c + 1) * G2_KC);
        compute(c & 1);
        if (c + 1 < G2_NC) store_stage((c + 1) & 1);
        __syncthreads();
    }

    #pragma unroll
    for (int i = 0; i < 2; i++) {
        int r0 = row0 + wm * 32 + i * 16 + (lane >> 2);
        #pragma unroll
        for (int j = 0; j < 4; j++) {
            int cidx = wn * 32 + j * 8 + (lane & 3) * 2;
            if (r0 < NN)
                *reinterpret_cast<float2*>(g_H1W1 + (size_t)r0 * FD + cidx) =
                    make_float2(acc[i][j][0], acc[i][j][1]);
            if (r0 + 8 < NN)
                *reinterpret_cast<float2*>(g_H1W1 + (size_t)(r0 + 8) * FD + cidx) =
                    make_float2(acc[i][j][2], acc[i][j][3]);
        }
    }
}

// ---------------- SpMM2 + softmax (fp32 gather, unroll 8) --------------------------
__global__ void __launch_bounds__(256) spmm2_softmax_kernel(float* __restrict__ out) {
    int w    = (blockIdx.x * blockDim.x + threadIdx.x) >> 5;
    int lane = threadIdx.x & 31;
    if (w >= NN) return;

    int s = g_rowptr[w], e = g_rowptr[w + 1];
    const float2* Y2 = reinterpret_cast<const float2*>(g_H1W1);

    float ax = 0.f, ay = 0.f;
    int i = s;
    for (; i + 8 <= e; i += 8) {
        int2 ed[8];
        float2 y[8];
        #pragma unroll
        for (int u = 0; u < 8; u++) ed[u] = g_cedge[i + u];
        #pragma unroll
        for (int u = 0; u < 8; u++) y[u] = Y2[(size_t)ed[u].x * 32 + lane];
        #pragma unroll
        for (int u = 0; u < 8; u++) {
            float v = __int_as_float(ed[u].y);
            ax = fmaf(v, y[u].x, ax);
            ay = fmaf(v, y[u].y, ay);
        }
    }
    for (; i + 4 <= e; i += 4) {
        int2 e0 = g_cedge[i],     e1 = g_cedge[i + 1];
        int2 e2 = g_cedge[i + 2], e3 = g_cedge[i + 3];
        float2 y0 = Y2[(size_t)e0.x * 32 + lane];
        float2 y1 = Y2[(size_t)e1.x * 32 + lane];
        float2 y2 = Y2[(size_t)e2.x * 32 + lane];
        float2 y3 = Y2[(size_t)e3.x * 32 + lane];
        float v0 = __int_as_float(e0.y), v1 = __int_as_float(e1.y);
        float v2 = __int_as_float(e2.y), v3 = __int_as_float(e3.y);
        ax = fmaf(v0, y0.x, ax); ay = fmaf(v0, y0.y, ay);
        ax = fmaf(v1, y1.x, ax); ay = fmaf(v1, y1.y, ay);
        ax = fmaf(v2, y2.x, ax); ay = fmaf(v2, y2.y, ay);
        ax = fmaf(v3, y3.x, ax); ay = fmaf(v3, y3.y, ay);
    }
    for (; i < e; i++) {
        int2 ed = g_cedge[i];
        float v = __int_as_float(ed.y);
        float2 y = Y2[(size_t)ed.x * 32 + lane];
        ax = fmaf(v, y.x, ax); ay = fmaf(v, y.y, ay);
    }

    float m = fmaxf(ax, ay);
    #pragma unroll
    for (int o = 16; o; o >>= 1) m = fmaxf(m, __shfl_xor_sync(0xffffffffu, m, o));
    float e0 = expf(ax - m), e1 = expf(ay - m);
    float sum = e0 + e1;
    #pragma unroll
    for (int o = 16; o; o >>= 1) sum += __shfl_xor_sync(0xffffffffu, sum, o);
    float inv = 1.f / sum;

    reinterpret_cast<float2*>(out)[(size_t)w * 32 + lane] = make_float2(e0 * inv, e1 * inv);
}

// ---------------- launcher ----------------------------------------------------------
extern "C" void kernel_launch(void* const* d_in, const int* in_sizes, int n_in,
                              void* d_out, int out_size) {
    const float* X  = (const float*)d_in[0];
    const int*   er = (const int*)d_in[1];
    const int*   ec = (const int*)d_in[2];
    const float* ev = (const float*)d_in[3];
    const float* W0 = (const float*)d_in[4];
    const float* W1 = (const float*)d_in[5];
    float* out = (float*)d_out;

    static cudaStream_t sB = nullptr;
    static cudaEvent_t evFork = nullptr, evCSR = nullptr;
    static bool init_done = false;
    if (!init_done) {
        cudaFuncSetAttribute(gemm1_mma_kernel,
                             cudaFuncAttributeMaxDynamicSharedMemorySize, G1_SMEM);
        cudaFuncSetAttribute(gemm2_mma_kernel,
                             cudaFuncAttributeMaxDynamicSharedMemorySize, G2_SMEM);
        cudaStreamCreateWithFlags(&sB, cudaStreamNonBlocking);
        cudaEventCreateWithFlags(&evFork, cudaEventDisableTiming);
        cudaEventCreateWithFlags(&evCSR, cudaEventDisableTiming);
        init_done = true;
    }

    // Fork: CSR build on side stream sB, concurrent with weight prep + GEMM1.
    cudaEventRecord(evFork, 0);
    cudaStreamWaitEvent(sB, evFork, 0);

    // --- branch B (sB): CSR build ---
    zero_cnt_kernel<<<(NN + 255) / 256, 256, 0, sB>>>();
    hist_kernel<<<(EE / 4 + 255) / 256, 256, 0, sB>>>((const int4*)er);
    scan_kernel<<<1, 1024, 0, sB>>>();
    scatter_kernel<<<(EE + 255) / 256, 256, 0, sB>>>(er, ec, ev);
    cudaEventRecord(evCSR, sB);

    // --- branch A (main): weight prep (merged) + GEMM1 ---
    wprep_kernel<<<(K1 * HD + HD * FD + 255) / 256, 256>>>(W0, W1);
    {
        dim3 grid(HD / 128, (NN + 127) / 128);
        gemm1_mma_kernel<<<grid, 256, G1_SMEM>>>(X);
    }

    // Join: SpMM1 needs CSR + XW0h.
    cudaStreamWaitEvent(0, evCSR, 0);
    spmm1_relu_kernel<<<(NN * 32 + 255) / 256, 256>>>();

    // Layer 2 (sequential — overlap here was shown to be negative-sum).
    gemm2_mma_kernel<<<(NN + 127) / 128, 256, G2_SMEM>>>();
    spmm2_softmax_kernel<<<(NN * 32 + 255) / 256, 256>>>(out);
}

// round 17
// speedup vs baseline: 1.0575x; 1.0001x over previous
#include <cuda_runtime.h>
#include <cuda_bf16.h>
#include <cuda_fp16.h>
#include <cstdint>

#define NN 100000
#define EE 3200000
#define K1 512
#define HD 256
#define FD 64

// ---------------- scratch -----------------------------------------------------
__device__ __align__(16) __half g_XW0h[NN * HD];    // X @ W0 fp16 (51 MB)
__device__ __align__(16) float g_H1[NN * HD];       // relu(A @ XW0) fp32
__device__ __align__(16) float g_H1W1[NN * FD];     // logits precursor fp32
__device__ int   g_rowptr[NN + 1];
__device__ int   g_cursor[NN];
__device__ int   g_cnt[NN];
__device__ __align__(16) int2 g_cedge[EE];          // (col, valbits) fused
__device__ __align__(16) __half g_W0t_h[HD * K1];   // W0^T fp16 [256][512]
__device__ __align__(16) __nv_bfloat16 g_W1t_hi[FD * HD];  // W1^T split [64][256]
__device__ __align__(16) __nv_bfloat16 g_W1t_lo[FD * HD];

// ---------------- helpers ------------------------------------------------------
__device__ __forceinline__ uint32_t smem_u32(const void* p) {
    uint32_t a;
    asm("{ .reg .u64 t; cvta.to.shared.u64 t, %1; cvt.u32.u64 %0, t; }" : "=r"(a) : "l"(p));
    return a;
}
__device__ __forceinline__ void ldmx4(uint32_t* d, uint32_t addr) {
    asm volatile("ldmatrix.sync.aligned.m8n8.x4.shared.b16 {%0,%1,%2,%3}, [%4];"
                 : "=r"(d[0]), "=r"(d[1]), "=r"(d[2]), "=r"(d[3]) : "r"(addr));
}
__device__ __forceinline__ void mma16816h(float* c, const uint32_t* a, uint32_t b0, uint32_t b1) {
    asm volatile("mma.sync.aligned.m16n8k16.row.col.f32.f16.f16.f32 "
                 "{%0,%1,%2,%3}, {%4,%5,%6,%7}, {%8,%9}, {%0,%1,%2,%3};"
                 : "+f"(c[0]), "+f"(c[1]), "+f"(c[2]), "+f"(c[3])
                 : "r"(a[0]), "r"(a[1]), "r"(a[2]), "r"(a[3]), "r"(b0), "r"(b1));
}
__device__ __forceinline__ void mma16816b(float* c, const uint32_t* a, uint32_t b0, uint32_t b1) {
    asm volatile("mma.sync.aligned.m16n8k16.row.col.f32.bf16.bf16.f32 "
                 "{%0,%1,%2,%3}, {%4,%5,%6,%7}, {%8,%9}, {%0,%1,%2,%3};"
                 : "+f"(c[0]), "+f"(c[1]), "+f"(c[2]), "+f"(c[3])
                 : "r"(a[0]), "r"(a[1]), "r"(a[2]), "r"(a[3]), "r"(b0), "r"(b1));
}

// ---------------- CSR build -----------------------------------------------------
__global__ void hist_kernel(const int4* __restrict__ rows4) {
    int i = blockIdx.x * blockDim.x + threadIdx.x;
    if (i < EE / 4) {
        int4 r = rows4[i];
        atomicAdd(&g_cnt[r.x], 1);
        atomicAdd(&g_cnt[r.y], 1);
        atomicAdd(&g_cnt[r.z], 1);
        atomicAdd(&g_cnt[r.w], 1);
    }
}
__global__ void __launch_bounds__(1024) scan_kernel() {
    __shared__ int wsum[32];
    int tid = threadIdx.x;
    const int PER = 98;
    int base = tid * PER;
    int s = 0;
    for (int j = 0; j < PER; j++) {
        int i = base + j;
        if (i < NN) s += g_cnt[i];
    }
    int lane = tid & 31, wid = tid >> 5;
    int x = s;
    #pragma unroll
    for (int o = 1; o < 32; o <<= 1) {
        int t = __shfl_up_sync(0xffffffffu, x, o);
        if (lane >= o) x += t;
    }
    if (lane == 31) wsum[wid] = x;
    __syncthreads();
    if (wid == 0) {
        int w = wsum[lane];
        #pragma unroll
        for (int o = 1; o < 32; o <<= 1) {
            int t = __shfl_up_sync(0xffffffffu, w, o);
            if (lane >= o) w += t;
        }
        wsum[lane] = w;
    }
    __syncthreads();
    int excl = x - s + (wid > 0 ? wsum[wid - 1] : 0);
    int run = excl;
    for (int j = 0; j < PER; j++) {
        int i = base + j;
        if (i < NN) {
            g_rowptr[i] = run;
            g_cursor[i] = run;
            run += g_cnt[i];
        }
    }
    if (tid == 1023) g_rowptr[NN] = run;
}
__global__ void scatter_kernel(const int* __restrict__ rows,
                               const int* __restrict__ cols,
                               const float* __restrict__ vals) {
    int i = blockIdx.x * blockDim.x + threadIdx.x;
    if (i < EE) {
        int r = rows[i];
        int p = atomicAdd(&g_cursor[r], 1);
        g_cedge[p] = make_int2(cols[i], __float_as_int(vals[i]));
    }
}

// ---------------- weight prep (merged) --------------------------------------------
__global__ void wprep_kernel(const float* __restrict__ W0, const float* __restrict__ W1) {
    int i = blockIdx.x * blockDim.x + threadIdx.x;
    if (i < K1 * HD) {
        int k = i / HD, n = i % HD;
        g_W0t_h[n * K1 + k] = __float2half(W0[i]);
    } else {
        int j = i - K1 * HD;
        if (j < HD * FD) {
            int k = j / FD, n = j % FD;
            float v = W1[j];
            __nv_bfloat16 h = __float2bfloat16(v);
            g_W1t_hi[n * HD + k] = h;
            g_W1t_lo[n * HD + k] = __float2bfloat16(v - __bfloat162float(h));
        }
    }
}

// ---------------- GEMM1 via mma.sync fp16, fp16 out ------------------------------
#define G1_KC   32
#define G1_NC   (K1 / G1_KC)
#define G1_STR  40
#define G1_BUF  20480                  // A 10240 | B 10240
#define G1_SMEM (2 * G1_BUF)

__global__ void __launch_bounds__(256, 2) gemm1_mma_kernel(const float* __restrict__ A) {
    extern __shared__ __align__(16) char smem[];
    uint32_t sb = smem_u32(smem);

    int tid  = threadIdx.x;
    int lane = tid & 31;
    int wid  = tid >> 5;
    int wm   = wid >> 2;
    int wn   = wid & 3;
    int row0 = blockIdx.y * 128;
    int col0 = blockIdx.x * 128;

    int a_row = tid >> 3;
    int a_kc  = (tid & 7) * 4;
    int b_row = tid >> 1;
    int b_kc  = (tid & 1) * 16;

    float4 aS[4];
    uint4  bS[2];

    uint32_t a_ld_off = (uint32_t)((wm * 64 + (lane & 15)) * G1_STR + ((lane >> 4) << 3)) * 2;
    uint32_t b_ld_off = (uint32_t)((wn * 32 + (lane & 7) + ((lane >> 4) << 3)) * G1_STR
                                   + (((lane >> 3) & 1) << 3)) * 2;

    float acc[4][4][4];
    #pragma unroll
    for (int i = 0; i < 4; i++)
        #pragma unroll
        for (int j = 0; j < 4; j++)
            #pragma unroll
            for (int t = 0; t < 4; t++) acc[i][j][t] = 0.f;

    auto load_stage = [&](int kt) {
        #pragma unroll
        for (int p = 0; p < 4; p++) {
            int r = row0 + a_row + p * 32;
            aS[p] = (r < NN)
                ? *reinterpret_cast<const float4*>(A + (size_t)r * K1 + kt + a_kc)
                : make_float4(0.f, 0.f, 0.f, 0.f);
        }
        int n = col0 + b_row;
        #pragma unroll
        for (int p = 0; p < 2; p++)
            bS[p] = *reinterpret_cast<const uint4*>(g_W0t_h + (size_t)n * K1 + kt + b_kc + p * 8);
    };

    auto store_stage = [&](int buf) {
        char* base = smem + buf * G1_BUF;
        #pragma unroll
        for (int p = 0; p < 4; p++) {
            float4 v = aS[p];
            __half2 h01 = __floats2half2_rn(v.x, v.y);
            __half2 h23 = __floats2half2_rn(v.z, v.w);
            uint32_t off = (uint32_t)((a_row + p * 32) * G1_STR + a_kc) * 2;
            *reinterpret_cast<uint2*>(base + off) =
                make_uint2(*(uint32_t*)&h01, *(uint32_t*)&h23);
        }
        #pragma unroll
        for (int p = 0; p < 2; p++) {
            uint32_t off = (uint32_t)(b_row * G1_STR + b_kc + p * 8) * 2;
            *reinterpret_cast<uint4*>(base + 10240 + off) = bS[p];
        }
    };

    auto compute = [&](int buf) {
        uint32_t ab = sb + buf * G1_BUF;
        #pragma unroll
        for (int ks = 0; ks < 2; ks++) {
            uint32_t kso = (uint32_t)(ks * 16) * 2;
            uint32_t ah[4][4], bh[4][2];
            #pragma unroll
            for (int i = 0; i < 4; i++) {
                uint32_t ao = ab + a_ld_off + kso + (uint32_t)(i * 16 * G1_STR) * 2;
                ldmx4(ah[i], ao);
            }
            #pragma unroll
            for (int j2 = 0; j2 < 2; j2++) {
                uint32_t bo = ab + 10240 + b_ld_off + kso + (uint32_t)(j2 * 16 * G1_STR) * 2;
                uint32_t t[4];
                ldmx4(t, bo);
                bh[j2 * 2][0] = t[0]; bh[j2 * 2][1] = t[1];
                bh[j2 * 2 + 1][0] = t[2]; bh[j2 * 2 + 1][1] = t[3];
            }
            #pragma unroll
            for (int i = 0; i < 4; i++)
                #pragma unroll
                for (int j = 0; j < 4; j++)
                    mma16816h(acc[i][j], ah[i], bh[j][0], bh[j][1]);
        }
    };

    load_stage(0);
    store_stage(0);
    __syncthreads();

    for (int c = 0; c < G1_NC; c++) {
        if (c + 1 < G1_NC) load_stage((c + 1) * G1_KC);
        compute(c & 1);
        if (c + 1 < G1_NC) store_stage((c + 1) & 1);
        __syncthreads();
    }

    #pragma unroll
    for (int i = 0; i < 4; i++) {
        int r0 = row0 + wm * 64 + i * 16 + (lane >> 2);
        #pragma unroll
        for (int j = 0; j < 4; j++) {
            int cidx = col0 + wn * 32 + j * 8 + (lane & 3) * 2;
            if (r0 < NN)
                *reinterpret_cast<__half2*>(g_XW0h + (size_t)r0 * HD + cidx) =
                    __floats2half2_rn(acc[i][j][0], acc[i][j][1]);
            if (r0 + 8 < NN)
                *reinterpret_cast<__half2*>(g_XW0h + (size_t)(r0 + 8) * HD + cidx) =
                    __floats2half2_rn(acc[i][j][2], acc[i][j][3]);
        }
    }
}

// ---------------- SpMM1: H1 = relu(A @ XW0h) -> fp32, warp per row ----------------
__device__ __forceinline__ void fmah8(float* acc, float v, const uint4& q) {
    const __half2* h = reinterpret_cast<const __half2*>(&q);
    #pragma unroll
    for (int t = 0; t < 4; t++) {
        float2 f = __half22float2(h[t]);
        acc[2 * t]     = fmaf(v, f.x, acc[2 * t]);
        acc[2 * t + 1] = fmaf(v, f.y, acc[2 * t + 1]);
    }
}

__global__ void __launch_bounds__(256) spmm1_relu_kernel() {
    int w    = (blockIdx.x * blockDim.x + threadIdx.x) >> 5;
    int lane = threadIdx.x & 31;
    if (w >= NN) return;

    int s = g_rowptr[w], e = g_rowptr[w + 1];
    const uint4* Yh = reinterpret_cast<const uint4*>(g_XW0h);

    float acc[8];
    #pragma unroll
    for (int t = 0; t < 8; t++) acc[t] = 0.f;

    int i = s;
    for (; i + 8 <= e; i += 8) {
        int2 ed[8];
        uint4 q[8];
        #pragma unroll
        for (int u = 0; u < 8; u++) ed[u] = g_cedge[i + u];
        #pragma unroll
        for (int u = 0; u < 8; u++) q[u] = Yh[(size_t)ed[u].x * 32 + lane];
        #pragma unroll
        for (int u = 0; u < 8; u++) fmah8(acc, __int_as_float(ed[u].y), q[u]);
    }
    for (; i + 4 <= e; i += 4) {
        int2 e0 = g_cedge[i],     e1 = g_cedge[i + 1];
        int2 e2 = g_cedge[i + 2], e3 = g_cedge[i + 3];
        uint4 q0 = Yh[(size_t)e0.x * 32 + lane];
        uint4 q1 = Yh[(size_t)e1.x * 32 + lane];
        uint4 q2 = Yh[(size_t)e2.x * 32 + lane];
        uint4 q3 = Yh[(size_t)e3.x * 32 + lane];
        fmah8(acc, __int_as_float(e0.y), q0);
        fmah8(acc, __int_as_float(e1.y), q1);
        fmah8(acc, __int_as_float(e2.y), q2);
        fmah8(acc, __int_as_float(e3.y), q3);
    }
    for (; i < e; i++) {
        int2 ed = g_cedge[i];
        uint4 q = Yh[(size_t)ed.x * 32 + lane];
        fmah8(acc, __int_as_float(ed.y), q);
    }

    float* dst = g_H1 + (size_t)w * HD + lane * 8;
    *reinterpret_cast<float4*>(dst) =
        make_float4(fmaxf(acc[0], 0.f), fmaxf(acc[1], 0.f),
                    fmaxf(acc[2], 0.f), fmaxf(acc[3], 0.f));
    *reinterpret_cast<float4*>(dst + 4) =
        make_float4(fmaxf(acc[4], 0.f), fmaxf(acc[5], 0.f),
                    fmaxf(acc[6], 0.f), fmaxf(acc[7], 0.f));
}

// ---------------- GEMM2 via mma.sync split-bf16 (3 products): fp32 in/out ---------
#define G2_KC   32
#define G2_NC   (HD / G2_KC)          // 8
#define G2_STR  40
#define G2_AH   0
#define G2_AL   10240
#define G2_BH   20480
#define G2_BL   25600
#define G2_BUF  30720
#define G2_SMEM (2 * G2_BUF)

__global__ void __launch_bounds__(256) gemm2_mma_kernel() {
    extern __shared__ __align__(16) char smem[];
    uint32_t sb = smem_u32(smem);

    int tid  = threadIdx.x;
    int lane = tid & 31;
    int wid  = tid >> 5;
    int wm   = wid >> 1;
    int wn   = wid & 1;
    int row0 = blockIdx.x * 128;

    int ar8   = tid >> 3;
    int ac8   = (tid & 7) * 4;
    int b_row = tid >> 2;
    int b_kc  = (tid & 3) * 8;

    float4 aS[4];
    uint4  bhS, blS;

    uint32_t a_ld_off = (uint32_t)((wm * 32 + (lane & 15)) * G2_STR + ((lane >> 4) << 3)) * 2;
    uint32_t b_ld_off = (uint32_t)((wn * 32 + (lane & 7) + ((lane >> 4) << 3)) * G2_STR
                                   + (((lane >> 3) & 1) << 3)) * 2;

    float acc[2][4][4];
    #pragma unroll
    for (int i = 0; i < 2; i++)
        #pragma unroll
        for (int j = 0; j < 4; j++)
            #pragma unroll
            for (int t = 0; t < 4; t++) acc[i][j][t] = 0.f;

    auto load_stage = [&](int kt) {
        #pragma unroll
        for (int p = 0; p < 4; p++) {
            int r = row0 + ar8 + p * 32;
            aS[p] = (r < NN)
                ? *reinterpret_cast<const float4*>(g_H1 + (size_t)r * HD + kt + ac8)
                : make_float4(0.f, 0.f, 0.f, 0.f);
        }
        bhS = *reinterpret_cast<const uint4*>(g_W1t_hi + (size_t)b_row * HD + kt + b_kc);
        blS = *reinterpret_cast<const uint4*>(g_W1t_lo + (size_t)b_row * HD + kt + b_kc);
    };

    auto store_stage = [&](int buf) {
        char* base = smem + buf * G2_BUF;
        #pragma unroll
        for (int p = 0; p < 4; p++) {
            float4 v = aS[p];
            __nv_bfloat162 h01 = __floats2bfloat162_rn(v.x, v.y);
            __nv_bfloat162 h23 = __floats2bfloat162_rn(v.z, v.w);
            float2 f01 = __bfloat1622float2(h01);
            float2 f23 = __bfloat1622float2(h23);
            __nv_bfloat162 l01 = __floats2bfloat162_rn(v.x - f01.x, v.y - f01.y);
            __nv_bfloat162 l23 = __floats2bfloat162_rn(v.z - f23.x, v.w - f23.y);
            uint32_t off = (uint32_t)((ar8 + p * 32) * G2_STR + ac8) * 2;
            *reinterpret_cast<uint2*>(base + G2_AH + off) =
                make_uint2(*(uint32_t*)&h01, *(uint32_t*)&h23);
            *reinterpret_cast<uint2*>(base + G2_AL + off) =
                make_uint2(*(uint32_t*)&l01, *(uint32_t*)&l23);
        }
        uint32_t boff = (uint32_t)(b_row * G2_STR + b_kc) * 2;
        *reinterpret_cast<uint4*>(base + G2_BH + boff) = bhS;
        *reinterpret_cast<uint4*>(base + G2_BL + boff) = blS;
    };

    auto compute = [&](int buf) {
        uint32_t ab = sb + buf * G2_BUF;
        #pragma unroll
        for (int ks = 0; ks < 2; ks++) {
            uint32_t kso = (uint32_t)(ks * 16) * 2;
            uint32_t ah[2][4], al[2][4], bh[4][2], bl[4][2];
            #pragma unroll
            for (int i = 0; i < 2; i++) {
                uint32_t ao = ab + a_ld_off + kso + (uint32_t)(i * 16 * G2_STR) * 2;
                ldmx4(ah[i], ao + G2_AH);
                ldmx4(al[i], ao + G2_AL);
            }
            #pragma unroll
            for (int j2 = 0; j2 < 2; j2++) {
                uint32_t bo = ab + b_ld_off + kso + (uint32_t)(j2 * 16 * G2_STR) * 2;
                uint32_t t[4];
                ldmx4(t, bo + G2_BH);
                bh[j2 * 2][0] = t[0]; bh[j2 * 2][1] = t[1];
                bh[j2 * 2 + 1][0] = t[2]; bh[j2 * 2 + 1][1] = t[3];
                ldmx4(t, bo + G2_BL);
                bl[j2 * 2][0] = t[0]; bl[j2 * 2][1] = t[1];
                bl[j2 * 2 + 1][0] = t[2]; bl[j2 * 2 + 1][1] = t[3];
            }
            #pragma unroll
            for (int i = 0; i < 2; i++)
                #pragma unroll
                for (int j = 0; j < 4; j++) {
                    mma16816b(acc[i][j], ah[i], bh[j][0], bh[j][1]);
                    mma16816b(acc[i][j], ah[i], bl[j][0], bl[j][1]);
                    mma16816b(acc[i][j], al[i], bh[j][0], bh[j][1]);
                }
        }
    };

    load_stage(0);
    store_stage(0);
    __syncthreads();

    for (int c = 0; c < G2_NC; c++) {
        if (c + 1 < G2_NC) load_stage((c + 1) * G2_KC);
        compute(c & 1);
        if (c + 1 < G2_NC) store_stage((c + 1) & 1);
        __syncthreads();
    }

    #pragma unroll
    for (int i = 0; i < 2; i++) {
        int r0 = row0 + wm * 32 + i * 16 + (lane >> 2);
        #pragma unroll
        for (int j = 0; j < 4; j++) {
            int cidx = wn * 32 + j * 8 + (lane & 3) * 2;
            if (r0 < NN)
                *reinterpret_cast<float2*>(g_H1W1 + (size_t)r0 * FD + cidx) =
                    make_float2(acc[i][j][0], acc[i][j][1]);
            if (r0 + 8 < NN)
                *reinterpret_cast<float2*>(g_H1W1 + (size_t)(r0 + 8) * FD + cidx) =
                    make_float2(acc[i][j][2], acc[i][j][3]);
        }
    }
}

// ---------------- SpMM2 + softmax (fp32 gather, unroll 16) -------------------------
__global__ void __launch_bounds__(256) spmm2_softmax_kernel(float* __restrict__ out) {
    int w    = (blockIdx.x * blockDim.x + threadIdx.x) >> 5;
    int lane = threadIdx.x & 31;
    if (w >= NN) return;

    int s = g_rowptr[w], e = g_rowptr[w + 1];
    const float2* Y2 = reinterpret_cast<const float2*>(g_H1W1);

    float ax = 0.f, ay = 0.f;
    int i = s;
    for (; i + 16 <= e; i += 16) {
        int2 ed[16];
        float2 y[16];
        #pragma unroll
        for (int u = 0; u < 16; u++) ed[u] = g_cedge[i + u];
        #pragma unroll
        for (int u = 0; u < 16; u++) y[u] = Y2[(size_t)ed[u].x * 32 + lane];
        #pragma unroll
        for (int u = 0; u < 16; u++) {
            float v = __int_as_float(ed[u].y);
            ax = fmaf(v, y[u].x, ax);
            ay = fmaf(v, y[u].y, ay);
        }
    }
    for (; i + 4 <= e; i += 4) {
        int2 e0 = g_cedge[i],     e1 = g_cedge[i + 1];
        int2 e2 = g_cedge[i + 2], e3 = g_cedge[i + 3];
        float2 y0 = Y2[(size_t)e0.x * 32 + lane];
        float2 y1 = Y2[(size_t)e1.x * 32 + lane];
        float2 y2 = Y2[(size_t)e2.x * 32 + lane];
        float2 y3 = Y2[(size_t)e3.x * 32 + lane];
        float v0 = __int_as_float(e0.y), v1 = __int_as_float(e1.y);
        float v2 = __int_as_float(e2.y), v3 = __int_as_float(e3.y);
        ax = fmaf(v0, y0.x, ax); ay = fmaf(v0, y0.y, ay);
        ax = fmaf(v1, y1.x, ax); ay = fmaf(v1, y1.y, ay);
        ax = fmaf(v2, y2.x, ax); ay = fmaf(v2, y2.y, ay);
        ax = fmaf(v3, y3.x, ax); ay = fmaf(v3, y3.y, ay);
    }
    for (; i < e; i++) {
        int2 ed = g_cedge[i];
        float v = __int_as_float(ed.y);
        float2 y = Y2[(size_t)ed.x * 32 + lane];
        ax = fmaf(v, y.x, ax); ay = fmaf(v, y.y, ay);
    }

    float m = fmaxf(ax, ay);
    #pragma unroll
    for (int o = 16; o; o >>= 1) m = fmaxf(m, __shfl_xor_sync(0xffffffffu, m, o));
    float e0 = expf(ax - m), e1 = expf(ay - m);
    float sum = e0 + e1;
    #pragma unroll
    for (int o = 16; o; o >>= 1) sum += __shfl_xor_sync(0xffffffffu, sum, o);
    float inv = 1.f / sum;

    reinterpret_cast<float2*>(out)[(size_t)w * 32 + lane] = make_float2(e0 * inv, e1 * inv);
}

// ---------------- launcher ----------------------------------------------------------
extern "C" void kernel_launch(void* const* d_in, const int* in_sizes, int n_in,
                              void* d_out, int out_size) {
    const float* X  = (const float*)d_in[0];
    const int*   er = (const int*)d_in[1];
    const int*   ec = (const int*)d_in[2];
    const float* ev = (const float*)d_in[3];
    const float* W0 = (const float*)d_in[4];
    const float* W1 = (const float*)d_in[5];
    float* out = (float*)d_out;

    static cudaStream_t sB = nullptr;
    static cudaEvent_t evFork = nullptr, evCSR = nullptr;
    static void* cnt_ptr = nullptr;
    static bool init_done = false;
    if (!init_done) {
        cudaFuncSetAttribute(gemm1_mma_kernel,
                             cudaFuncAttributeMaxDynamicSharedMemorySize, G1_SMEM);
        cudaFuncSetAttribute(gemm2_mma_kernel,
                             cudaFuncAttributeMaxDynamicSharedMemorySize, G2_SMEM);
        cudaStreamCreateWithFlags(&sB, cudaStreamNonBlocking);
        cudaEventCreateWithFlags(&evFork, cudaEventDisableTiming);
        cudaEventCreateWithFlags(&evCSR, cudaEventDisableTiming);
        cudaGetSymbolAddress(&cnt_ptr, g_cnt);
        init_done = true;
    }

    // Fork: CSR build on side stream sB, concurrent with weight prep + GEMM1.
    cudaEventRecord(evFork, 0);
    cudaStreamWaitEvent(sB, evFork, 0);

    // --- branch B (sB): CSR build ---
    cudaMemsetAsync(cnt_ptr, 0, NN * sizeof(int), sB);
    hist_kernel<<<(EE / 4 + 255) / 256, 256, 0, sB>>>((const int4*)er);
    scan_kernel<<<1, 1024, 0, sB>>>();
    scatter_kernel<<<(EE + 255) / 256, 256, 0, sB>>>(er, ec, ev);
    cudaEventRecord(evCSR, sB);

    // --- branch A (main): weight prep (merged) + GEMM1 ---
    wprep_kernel<<<(K1 * HD + HD * FD + 255) / 256, 256>>>(W0, W1);
    {
        dim3 grid(HD / 128, (NN + 127) / 128);
        gemm1_mma_kernel<<<grid, 256, G1_SMEM>>>(X);
    }

    // Join: SpMM1 needs CSR + XW0h.
    cudaStreamWaitEvent(0, evCSR, 0);
    spmm1_relu_kernel<<<(NN * 32 + 255) / 256, 256>>>();

    // Layer 2 (sequential — overlap here was shown to be negative-sum).
    gemm2_mma_kernel<<<(NN + 127) / 128, 256, G2_SMEM>>>();
    spmm2_softmax_kernel<<<(NN * 32 + 255) / 256, 256>>>(out);
}